// round 1
// baseline (speedup 1.0000x reference)
#include <cuda_runtime.h>
#include <cuda_bf16.h>
#include <math_constants.h>

// Problem constants
#define Bq 4
#define Ss 1024
#define Ee 1024
#define Hh 16
#define DKk 64

// Scratch (device globals; no allocations allowed)
__device__ float g_Q[(size_t)Bq * Ss * Ee];                 // 16 MiB
__device__ float g_K[(size_t)Bq * Ss * Ee];                 // 16 MiB
__device__ float g_attn[(size_t)Bq * Hh * Ss * Ss];        // 256 MiB, layout [b][q][h][k]

// ---------------------------------------------------------------------------
// SGEMM NT: C[M,N] = A[M,K] * B[N,K]^T + bias[N]
// A row-major [M,K], B row-major [N,K] (K contiguous for both -> coalesced)
// Block tile 128x128, K-tile 16, 256 threads, 8x8 per thread.
// ---------------------------------------------------------------------------
__global__ __launch_bounds__(256)
void sgemm_nt(const float* __restrict__ A, const float* __restrict__ Bm,
              const float* __restrict__ bias, float* __restrict__ C,
              int M, int N, int K) {
    __shared__ float As[16][128];
    __shared__ float Bs[16][128];

    const int tid = threadIdx.x;
    const int bm = blockIdx.y * 128;
    const int bn = blockIdx.x * 128;

    const int tr = tid >> 4;          // 0..15
    const int tc = tid & 15;          // 0..15
    const int m0 = tr * 8;
    const int n0 = tc * 8;

    const int lr = tid >> 2;          // 0..63
    const int lc = (tid & 3) * 4;     // 0,4,8,12

    float acc[8][8];
#pragma unroll
    for (int i = 0; i < 8; ++i)
#pragma unroll
        for (int j = 0; j < 8; ++j) acc[i][j] = 0.0f;

    for (int k0 = 0; k0 < K; k0 += 16) {
#pragma unroll
        for (int it = 0; it < 2; ++it) {
            const int r = lr + it * 64;
            float4 va = *(const float4*)&A[(size_t)(bm + r) * K + k0 + lc];
            As[lc + 0][r] = va.x; As[lc + 1][r] = va.y;
            As[lc + 2][r] = va.z; As[lc + 3][r] = va.w;
            float4 vb = *(const float4*)&Bm[(size_t)(bn + r) * K + k0 + lc];
            Bs[lc + 0][r] = vb.x; Bs[lc + 1][r] = vb.y;
            Bs[lc + 2][r] = vb.z; Bs[lc + 3][r] = vb.w;
        }
        __syncthreads();

#pragma unroll
        for (int k = 0; k < 16; ++k) {
            float ra[8], rb[8];
            *(float4*)&ra[0] = *(const float4*)&As[k][m0];
            *(float4*)&ra[4] = *(const float4*)&As[k][m0 + 4];
            *(float4*)&rb[0] = *(const float4*)&Bs[k][n0];
            *(float4*)&rb[4] = *(const float4*)&Bs[k][n0 + 4];
#pragma unroll
            for (int i = 0; i < 8; ++i)
#pragma unroll
                for (int j = 0; j < 8; ++j)
                    acc[i][j] = fmaf(ra[i], rb[j], acc[i][j]);
        }
        __syncthreads();
    }

#pragma unroll
    for (int i = 0; i < 8; ++i) {
        const int m = bm + m0 + i;
#pragma unroll
        for (int j = 0; j < 8; j += 4) {
            const int n = bn + n0 + j;
            float4 o;
            o.x = acc[i][j + 0] + bias[n + 0];
            o.y = acc[i][j + 1] + bias[n + 1];
            o.z = acc[i][j + 2] + bias[n + 2];
            o.w = acc[i][j + 3] + bias[n + 3];
            *(float4*)&C[(size_t)m * N + n] = o;
        }
    }
}

// ---------------------------------------------------------------------------
// Attention scores + mask + softmax, fused.
// Grid: (S/32 qtiles, H, B). Block: 256 threads.
// Each block: 32 q-rows x full 1024 k-cols for one (b,h).
// scores kept in dynamic smem (128 KiB); K tiles staged (padded, conflict-free).
// Writes normalized probabilities into g_attn[b][q][h][k].
// ---------------------------------------------------------------------------
#define BQ 32
__global__ __launch_bounds__(256)
void attn_softmax_kernel(const int* __restrict__ mask) {
    __shared__ float Qs[BQ][64];      // [q][d]
    __shared__ float Ks[128][65];     // [k][d], padded -> conflict-free lane reads
    extern __shared__ float scores[]; // [BQ][1024]

    const int b  = blockIdx.z;
    const int h  = blockIdx.y;
    const int q0 = blockIdx.x * BQ;
    const int tid = threadIdx.x;

    // Load Q tile (coalesced)
    for (int i = tid; i < BQ * 64; i += 256) {
        const int q = i >> 6, d = i & 63;
        Qs[q][d] = g_Q[((size_t)(b * Ss + q0 + q)) * Ee + h * DKk + d];
    }

    const int tq = tid >> 5;   // 0..7  -> q rows tq*4 + i
    const int tk = tid & 31;   // k cols: tk + 32*j

    for (int kt = 0; kt < Ss / 128; ++kt) {
        __syncthreads();
        // Stage K tile: 128 rows x 64 cols
        for (int i = tid; i < 128 * 16; i += 256) {
            const int kr = i >> 4, c4 = (i & 15) * 4;
            float4 v = *(const float4*)&g_K[((size_t)(b * Ss + kt * 128 + kr)) * Ee + h * DKk + c4];
            Ks[kr][c4 + 0] = v.x; Ks[kr][c4 + 1] = v.y;
            Ks[kr][c4 + 2] = v.z; Ks[kr][c4 + 3] = v.w;
        }
        __syncthreads();

        float acc[4][4];
#pragma unroll
        for (int i = 0; i < 4; ++i)
#pragma unroll
            for (int j = 0; j < 4; ++j) acc[i][j] = 0.0f;

#pragma unroll 8
        for (int d = 0; d < 64; ++d) {
            float a[4], kk[4];
#pragma unroll
            for (int i = 0; i < 4; ++i) a[i] = Qs[tq * 4 + i][d];     // broadcast
#pragma unroll
            for (int j = 0; j < 4; ++j) kk[j] = Ks[tk + 32 * j][d];   // pad-65 -> no conflict
#pragma unroll
            for (int i = 0; i < 4; ++i)
#pragma unroll
                for (int j = 0; j < 4; ++j)
                    acc[i][j] = fmaf(a[i], kk[j], acc[i][j]);
        }

#pragma unroll
        for (int i = 0; i < 4; ++i)
#pragma unroll
            for (int j = 0; j < 4; ++j)
                scores[(tq * 4 + i) * Ss + kt * 128 + tk + 32 * j] = acc[i][j];
    }
    __syncthreads();

    // Mask + scale (1/sqrt(64) = 0.125), linear & coalesced.
    // mask rows for q0..q0+31 are contiguous: offset (b*S + q0)*S + i
    const int* mrow = mask + ((size_t)(b * Ss + q0)) * Ss;
    for (int i = tid; i < BQ * Ss; i += 256) {
        const float s = scores[i];
        scores[i] = mrow[i] ? s * 0.125f : -1e9f;
    }
    __syncthreads();

    // Softmax: 8-lane team per row (32 rows x 8 lanes = 256 threads)
    const int row  = tid >> 3;
    const int lane = tid & 7;
    float* sr = scores + row * Ss;

    float mx = -CUDART_INF_F;
    for (int c = lane; c < Ss; c += 8) mx = fmaxf(mx, sr[c]);
#pragma unroll
    for (int o = 4; o > 0; o >>= 1)
        mx = fmaxf(mx, __shfl_xor_sync(0xffffffffu, mx, o, 8));

    float sum = 0.0f;
    for (int c = lane; c < Ss; c += 8) {
        const float e = __expf(sr[c] - mx);
        sr[c] = e;
        sum += e;
    }
#pragma unroll
    for (int o = 4; o > 0; o >>= 1)
        sum += __shfl_xor_sync(0xffffffffu, sum, o, 8);
    const float inv = 1.0f / sum;

    // Write probabilities to g_attn[b][q][h][k] (row index = (b*S+q)*H + h)
    float* orow = g_attn + ((size_t)((b * Ss + q0 + row) * Hh + h)) * Ss;
    for (int c = lane; c < Ss; c += 8) orow[c] = sr[c] * inv;
}

// ---------------------------------------------------------------------------
extern "C" void kernel_launch(void* const* d_in, const int* in_sizes, int n_in,
                              void* d_out, int out_size) {
    const float* x   = (const float*)d_in[0];
    const int*   msk = (const int*)  d_in[1];
    const float* Wq  = (const float*)d_in[2];
    const float* bq  = (const float*)d_in[3];
    const float* Wk  = (const float*)d_in[4];
    const float* bk  = (const float*)d_in[5];
    // d_in[6], d_in[7] = Wv, bv : intentionally unused (reference discards V)
    const float* Wo  = (const float*)d_in[8];
    const float* bo  = (const float*)d_in[9];
    float* out = (float*)d_out;

    float *qbuf, *kbuf, *attnbuf;
    cudaGetSymbolAddress((void**)&qbuf, g_Q);
    cudaGetSymbolAddress((void**)&kbuf, g_K);
    cudaGetSymbolAddress((void**)&attnbuf, g_attn);

    // 1) Q, K projections: [4096,1024] @ W^T + b
    {
        dim3 grid(Ee / 128, (Bq * Ss) / 128);  // (8, 32)
        sgemm_nt<<<grid, 256>>>(x, Wq, bq, qbuf, Bq * Ss, Ee, Ee);
        sgemm_nt<<<grid, 256>>>(x, Wk, bk, kbuf, Bq * Ss, Ee, Ee);
    }

    // 2) Scores + mask + softmax -> g_attn
    {
        const size_t smem = (size_t)BQ * Ss * sizeof(float); // 128 KiB
        cudaFuncSetAttribute(attn_softmax_kernel,
                             cudaFuncAttributeMaxDynamicSharedMemorySize, (int)smem);
        dim3 grid(Ss / BQ, Hh, Bq);            // (32, 16, 4)
        attn_softmax_kernel<<<grid, 256, smem>>>(msk);
    }

    // 3) Output projection: attn[65536,1024] @ Wo^T + bo
    {
        const int M = Bq * Ss * Hh;            // 65536
        dim3 grid(Ee / 128, M / 128);          // (8, 512)
        sgemm_nt<<<grid, 256>>>(attnbuf, Wo, bo, out, M, Ee, Ee);
    }
}

// round 3
// speedup vs baseline: 1.9054x; 1.9054x over previous
#include <cuda_runtime.h>
#include <cuda_bf16.h>
#include <math_constants.h>
#include <cstdint>

// Problem constants
#define Bq 4
#define Ss 1024
#define Ee 1024
#define Hh 16
#define DKk 64

// ---------------------------------------------------------------------------
// Device scratch (no allocations allowed)
// ---------------------------------------------------------------------------
__device__ float g_Q[(size_t)Bq * Ss * Ee];                    // 16 MiB
__device__ float g_K[(size_t)Bq * Ss * Ee];                    // 16 MiB
__device__ __nv_bfloat16 g_Ahi[(size_t)Bq * Ss * Hh * Ss];     // 128 MiB
__device__ __nv_bfloat16 g_Alo[(size_t)Bq * Ss * Hh * Ss];     // 128 MiB
__device__ __nv_bfloat16 g_xhi[(size_t)Bq * Ss * Ee];          // 8 MiB
__device__ __nv_bfloat16 g_xlo[(size_t)Bq * Ss * Ee];          // 8 MiB
__device__ __nv_bfloat16 g_Wqhi[Ee * Ee], g_Wqlo[Ee * Ee];
__device__ __nv_bfloat16 g_Wkhi[Ee * Ee], g_Wklo[Ee * Ee];
__device__ __nv_bfloat16 g_Wohi[Ee * Ee], g_Wolo[Ee * Ee];

// ---------------------------------------------------------------------------
// PTX helpers (base ISA only: cp.async / ldmatrix / mma.sync — no 'a' features)
// ---------------------------------------------------------------------------
__device__ __forceinline__ uint32_t smem_u32(const void* p) {
    uint32_t a;
    asm("{ .reg .u64 t; cvta.to.shared.u64 t, %1; cvt.u32.u64 %0, t; }"
        : "=r"(a) : "l"(p));
    return a;
}
__device__ __forceinline__ void cp_async16(uint32_t saddr, const void* gaddr) {
    asm volatile("cp.async.cg.shared.global [%0], [%1], 16;"
                 :: "r"(saddr), "l"(gaddr) : "memory");
}
#define CP_COMMIT() asm volatile("cp.async.commit_group;" ::: "memory")
#define CP_WAIT(n)  asm volatile("cp.async.wait_group %0;" :: "n"(n) : "memory")

__device__ __forceinline__ void ldmat4(uint32_t& r0, uint32_t& r1,
                                       uint32_t& r2, uint32_t& r3, uint32_t addr) {
    asm volatile("ldmatrix.sync.aligned.m8n8.x4.shared.b16 {%0,%1,%2,%3}, [%4];"
                 : "=r"(r0), "=r"(r1), "=r"(r2), "=r"(r3) : "r"(addr));
}
__device__ __forceinline__ void mma16816(float* c, const uint32_t* a, const uint32_t* b) {
    asm volatile(
        "mma.sync.aligned.m16n8k16.row.col.f32.bf16.bf16.f32 "
        "{%0,%1,%2,%3}, {%4,%5,%6,%7}, {%8,%9}, {%0,%1,%2,%3};"
        : "+f"(c[0]), "+f"(c[1]), "+f"(c[2]), "+f"(c[3])
        : "r"(a[0]), "r"(a[1]), "r"(a[2]), "r"(a[3]), "r"(b[0]), "r"(b[1]));
}

// ---------------------------------------------------------------------------
// bf16x3 GEMM-NT:  C[M,N] = A[M,K] @ B[N,K]^T + bias[N]   (A,B pre-split hi/lo)
// 128x128 block tile, BK=32, 4-stage cp.async pipeline, 256 threads (8 warps 2x4).
// smem tile: 128 rows x 64B (4 x 16B chunks), swizzle chunk ^= (row>>1)&3.
// ---------------------------------------------------------------------------
#define BMt 128
#define BNt 128
#define BKt 32
#define NSTAGE 4
#define TILE_BYTES (128 * 64)          // one operand tile: 8 KiB
#define STAGE_BYTES (4 * TILE_BYTES)   // Ahi, Alo, Bhi, Blo: 32 KiB
#define GEMM_SMEM (NSTAGE * STAGE_BYTES)

__global__ __launch_bounds__(256, 1)
void gemm_bf16x3(const __nv_bfloat16* __restrict__ Ahi, const __nv_bfloat16* __restrict__ Alo,
                 const __nv_bfloat16* __restrict__ Bhi, const __nv_bfloat16* __restrict__ Blo,
                 const float* __restrict__ bias, float* __restrict__ C,
                 int M, int N, int K) {
    extern __shared__ char sm[];
    __shared__ float s_bias[BNt];

    const int tid  = threadIdx.x;
    const int lane = tid & 31;
    const int wid  = tid >> 5;
    const int warp_m = wid >> 2;   // 0..1  (64 rows each)
    const int warp_n = wid & 3;    // 0..3  (32 cols each)
    const int bm = blockIdx.y * BMt;
    const int bn = blockIdx.x * BNt;

    if (tid < BNt) s_bias[tid] = bias[bn + tid];

    const uint32_t smb = smem_u32(sm);

    // per-lane ldmatrix sub-tile decomposition
    const int sub   = lane >> 3;            // 0..3
    const int rlane = ((sub & 1) << 3) + (lane & 7);  // row within 16-row frag
    const int csub  = sub >> 1;             // 0..1: which 16B chunk (k half)

    // ---- cp.async stage loader ----
    auto load_stage = [&](int c) {
        const int k0 = c * BKt;
        const uint32_t stg = smb + (c % NSTAGE) * STAGE_BYTES;
#pragma unroll
        for (int i = 0; i < 8; ++i) {
            const int tile = i >> 1;                    // 0=Ahi 1=Alo 2=Bhi 3=Blo
            const int idx  = ((i & 1) << 8) + tid;      // 0..511
            const int r = idx >> 2, cc = idx & 3;
            const uint32_t so = stg + tile * TILE_BYTES + r * 64
                              + ((cc ^ ((r >> 1) & 3)) << 4);
            const __nv_bfloat16* src;
            size_t grow;
            if (tile == 0)      { src = Ahi; grow = (size_t)(bm + r); }
            else if (tile == 1) { src = Alo; grow = (size_t)(bm + r); }
            else if (tile == 2) { src = Bhi; grow = (size_t)(bn + r); }
            else                { src = Blo; grow = (size_t)(bn + r); }
            cp_async16(so, src + grow * K + k0 + cc * 8);
        }
        CP_COMMIT();
    };

    const int nk = K / BKt;
    for (int c = 0; c < NSTAGE - 1; ++c) load_stage(c);

    float acc[4][4][4];
#pragma unroll
    for (int mi = 0; mi < 4; ++mi)
#pragma unroll
        for (int ni = 0; ni < 4; ++ni)
#pragma unroll
            for (int j = 0; j < 4; ++j) acc[mi][ni][j] = 0.0f;

    for (int c = 0; c < nk; ++c) {
        CP_WAIT(NSTAGE - 2);
        __syncthreads();
        // prefetch chunk c+NSTAGE-1 into the buffer freed by chunk c-1
        if (c + NSTAGE - 1 < nk) load_stage(c + NSTAGE - 1);
        else CP_COMMIT();

        const uint32_t stg = smb + (c % NSTAGE) * STAGE_BYTES;
#pragma unroll
        for (int ks = 0; ks < 2; ++ks) {
            const int chunk = ks * 2 + csub;
            uint32_t ahi[4][4], alo[4][4], bhi[4][2], blo[4][2];
#pragma unroll
            for (int mi = 0; mi < 4; ++mi) {
                const int r = warp_m * 64 + mi * 16 + rlane;
                const uint32_t off = r * 64 + ((chunk ^ ((r >> 1) & 3)) << 4);
                ldmat4(ahi[mi][0], ahi[mi][1], ahi[mi][2], ahi[mi][3],
                       stg + 0 * TILE_BYTES + off);
                ldmat4(alo[mi][0], alo[mi][1], alo[mi][2], alo[mi][3],
                       stg + 1 * TILE_BYTES + off);
            }
#pragma unroll
            for (int nf = 0; nf < 2; ++nf) {
                const int r = warp_n * 32 + nf * 16 + rlane;
                const uint32_t off = r * 64 + ((chunk ^ ((r >> 1) & 3)) << 4);
                uint32_t q0, q1, q2, q3;
                ldmat4(q0, q1, q2, q3, stg + 2 * TILE_BYTES + off);
                bhi[nf * 2 + 0][0] = q0; bhi[nf * 2 + 0][1] = q2;
                bhi[nf * 2 + 1][0] = q1; bhi[nf * 2 + 1][1] = q3;
                ldmat4(q0, q1, q2, q3, stg + 3 * TILE_BYTES + off);
                blo[nf * 2 + 0][0] = q0; blo[nf * 2 + 0][1] = q2;
                blo[nf * 2 + 1][0] = q1; blo[nf * 2 + 1][1] = q3;
            }
#pragma unroll
            for (int mi = 0; mi < 4; ++mi)
#pragma unroll
                for (int ni = 0; ni < 4; ++ni) {
                    mma16816(acc[mi][ni], ahi[mi], bhi[ni]);
                    mma16816(acc[mi][ni], alo[mi], bhi[ni]);
                    mma16816(acc[mi][ni], ahi[mi], blo[ni]);
                }
        }
    }

    // ---- epilogue: fragment -> global, + bias ----
    const int r0 = (lane >> 2);
    const int c0 = (lane & 3) * 2;
#pragma unroll
    for (int mi = 0; mi < 4; ++mi) {
        const int gr0 = bm + warp_m * 64 + mi * 16 + r0;
#pragma unroll
        for (int ni = 0; ni < 4; ++ni) {
            const int gc = bn + warp_n * 32 + ni * 8 + c0;
            const int lc = warp_n * 32 + ni * 8 + c0;
            float2 v0, v1;
            v0.x = acc[mi][ni][0] + s_bias[lc];
            v0.y = acc[mi][ni][1] + s_bias[lc + 1];
            v1.x = acc[mi][ni][2] + s_bias[lc];
            v1.y = acc[mi][ni][3] + s_bias[lc + 1];
            *(float2*)&C[(size_t)gr0 * N + gc]       = v0;
            *(float2*)&C[(size_t)(gr0 + 8) * N + gc] = v1;
        }
    }
}

// ---------------------------------------------------------------------------
// fp32 -> bf16 hi/lo split (vectorized x4)
// ---------------------------------------------------------------------------
__global__ void split_f32_bf16(const float4* __restrict__ src,
                               __nv_bfloat162* __restrict__ hi,
                               __nv_bfloat162* __restrict__ lo, int n4) {
    int i = blockIdx.x * blockDim.x + threadIdx.x;
    if (i >= n4) return;
    float4 v = src[i];
    __nv_bfloat16 h0 = __float2bfloat16(v.x), h1 = __float2bfloat16(v.y);
    __nv_bfloat16 h2 = __float2bfloat16(v.z), h3 = __float2bfloat16(v.w);
    __nv_bfloat16 l0 = __float2bfloat16(v.x - __bfloat162float(h0));
    __nv_bfloat16 l1 = __float2bfloat16(v.y - __bfloat162float(h1));
    __nv_bfloat16 l2 = __float2bfloat16(v.z - __bfloat162float(h2));
    __nv_bfloat16 l3 = __float2bfloat16(v.w - __bfloat162float(h3));
    hi[i * 2 + 0] = __halves2bfloat162(h0, h1);
    hi[i * 2 + 1] = __halves2bfloat162(h2, h3);
    lo[i * 2 + 0] = __halves2bfloat162(l0, l1);
    lo[i * 2 + 1] = __halves2bfloat162(l2, l3);
}

// ---------------------------------------------------------------------------
// Attention scores + mask + softmax -> bf16 hi/lo probability matrix
// ---------------------------------------------------------------------------
#define BQ 32
__global__ __launch_bounds__(256)
void attn_softmax_kernel(const int* __restrict__ mask) {
    __shared__ float Qs[BQ][64];
    __shared__ float Ks[128][65];
    extern __shared__ float scores[];   // [BQ][1024]

    const int b = blockIdx.z;
    const int h = blockIdx.y;
    const int q0 = blockIdx.x * BQ;
    const int tid = threadIdx.x;

    for (int i = tid; i < BQ * 64; i += 256) {
        const int q = i >> 6, d = i & 63;
        Qs[q][d] = g_Q[((size_t)(b * Ss + q0 + q)) * Ee + h * DKk + d];
    }

    const int tq = tid >> 5;
    const int tk = tid & 31;

    for (int kt = 0; kt < Ss / 128; ++kt) {
        __syncthreads();
        for (int i = tid; i < 128 * 16; i += 256) {
            const int kr = i >> 4, c4 = (i & 15) * 4;
            float4 v = *(const float4*)&g_K[((size_t)(b * Ss + kt * 128 + kr)) * Ee + h * DKk + c4];
            Ks[kr][c4 + 0] = v.x; Ks[kr][c4 + 1] = v.y;
            Ks[kr][c4 + 2] = v.z; Ks[kr][c4 + 3] = v.w;
        }
        __syncthreads();

        float acc[4][4];
#pragma unroll
        for (int i = 0; i < 4; ++i)
#pragma unroll
            for (int j = 0; j < 4; ++j) acc[i][j] = 0.0f;

#pragma unroll 8
        for (int d = 0; d < 64; ++d) {
            float a[4], kk[4];
#pragma unroll
            for (int i = 0; i < 4; ++i) a[i] = Qs[tq * 4 + i][d];
#pragma unroll
            for (int j = 0; j < 4; ++j) kk[j] = Ks[tk + 32 * j][d];
#pragma unroll
            for (int i = 0; i < 4; ++i)
#pragma unroll
                for (int j = 0; j < 4; ++j)
                    acc[i][j] = fmaf(a[i], kk[j], acc[i][j]);
        }
#pragma unroll
        for (int i = 0; i < 4; ++i)
#pragma unroll
            for (int j = 0; j < 4; ++j)
                scores[(tq * 4 + i) * Ss + kt * 128 + tk + 32 * j] = acc[i][j];
    }
    __syncthreads();

    const int* mrow = mask + ((size_t)(b * Ss + q0)) * Ss;
    for (int i = tid; i < BQ * Ss; i += 256) {
        const float s = scores[i];
        scores[i] = mrow[i] ? s * 0.125f : -1e9f;
    }
    __syncthreads();

    const int row = tid >> 3;
    const int lane = tid & 7;
    float* sr = scores + row * Ss;

    float mx = -CUDART_INF_F;
    for (int c = lane; c < Ss; c += 8) mx = fmaxf(mx, sr[c]);
#pragma unroll
    for (int o = 4; o > 0; o >>= 1)
        mx = fmaxf(mx, __shfl_xor_sync(0xffffffffu, mx, o, 8));

    float sum = 0.0f;
    for (int c = lane; c < Ss; c += 8) {
        const float e = __expf(sr[c] - mx);
        sr[c] = e;
        sum += e;
    }
#pragma unroll
    for (int o = 4; o > 0; o >>= 1)
        sum += __shfl_xor_sync(0xffffffffu, sum, o, 8);
    const float inv = 1.0f / sum;

    const size_t rbase = ((size_t)((b * Ss + q0 + row) * Hh + h)) * Ss;
    __nv_bfloat16* hrow = g_Ahi + rbase;
    __nv_bfloat16* lrow = g_Alo + rbase;
    for (int c = lane; c < Ss; c += 8) {
        const float p = sr[c] * inv;
        const __nv_bfloat16 hv = __float2bfloat16(p);
        hrow[c] = hv;
        lrow[c] = __float2bfloat16(p - __bfloat162float(hv));
    }
}

// ---------------------------------------------------------------------------
extern "C" void kernel_launch(void* const* d_in, const int* in_sizes, int n_in,
                              void* d_out, int out_size) {
    const float* x   = (const float*)d_in[0];
    const int*   msk = (const int*)  d_in[1];
    const float* Wq  = (const float*)d_in[2];
    const float* bq  = (const float*)d_in[3];
    const float* Wk  = (const float*)d_in[4];
    const float* bk  = (const float*)d_in[5];
    // d_in[6], d_in[7] = Wv, bv : unused (reference discards V)
    const float* Wo  = (const float*)d_in[8];
    const float* bo  = (const float*)d_in[9];
    float* out = (float*)d_out;

    float *qbuf, *kbuf;
    __nv_bfloat16 *ahi, *alo, *xhi, *xlo;
    __nv_bfloat16 *wqhi, *wqlo, *wkhi, *wklo, *wohi, *wolo;
    cudaGetSymbolAddress((void**)&qbuf, g_Q);
    cudaGetSymbolAddress((void**)&kbuf, g_K);
    cudaGetSymbolAddress((void**)&ahi, g_Ahi);
    cudaGetSymbolAddress((void**)&alo, g_Alo);
    cudaGetSymbolAddress((void**)&xhi, g_xhi);
    cudaGetSymbolAddress((void**)&xlo, g_xlo);
    cudaGetSymbolAddress((void**)&wqhi, g_Wqhi);
    cudaGetSymbolAddress((void**)&wqlo, g_Wqlo);
    cudaGetSymbolAddress((void**)&wkhi, g_Wkhi);
    cudaGetSymbolAddress((void**)&wklo, g_Wklo);
    cudaGetSymbolAddress((void**)&wohi, g_Wohi);
    cudaGetSymbolAddress((void**)&wolo, g_Wolo);

    cudaFuncSetAttribute(gemm_bf16x3,
                         cudaFuncAttributeMaxDynamicSharedMemorySize, GEMM_SMEM);
    cudaFuncSetAttribute(attn_softmax_kernel,
                         cudaFuncAttributeMaxDynamicSharedMemorySize,
                         (int)(BQ * Ss * sizeof(float)));

    // 0) fp32 -> bf16 hi/lo splits
    {
        const int nx4 = Bq * Ss * Ee / 4;
        split_f32_bf16<<<(nx4 + 255) / 256, 256>>>((const float4*)x,
            (__nv_bfloat162*)xhi, (__nv_bfloat162*)xlo, nx4);
        const int nw4 = Ee * Ee / 4;
        split_f32_bf16<<<(nw4 + 255) / 256, 256>>>((const float4*)Wq,
            (__nv_bfloat162*)wqhi, (__nv_bfloat162*)wqlo, nw4);
        split_f32_bf16<<<(nw4 + 255) / 256, 256>>>((const float4*)Wk,
            (__nv_bfloat162*)wkhi, (__nv_bfloat162*)wklo, nw4);
        split_f32_bf16<<<(nw4 + 255) / 256, 256>>>((const float4*)Wo,
            (__nv_bfloat162*)wohi, (__nv_bfloat162*)wolo, nw4);
    }

    // 1) Q, K projections: [4096,1024] @ W^T + b
    {
        dim3 grid(Ee / BNt, (Bq * Ss) / BMt);   // (8, 32)
        gemm_bf16x3<<<grid, 256, GEMM_SMEM>>>(xhi, xlo, wqhi, wqlo, bq, qbuf,
                                              Bq * Ss, Ee, Ee);
        gemm_bf16x3<<<grid, 256, GEMM_SMEM>>>(xhi, xlo, wkhi, wklo, bk, kbuf,
                                              Bq * Ss, Ee, Ee);
    }

    // 2) Scores + mask + softmax -> bf16 hi/lo probabilities
    {
        const size_t smem = (size_t)BQ * Ss * sizeof(float);
        dim3 grid(Ss / BQ, Hh, Bq);
        attn_softmax_kernel<<<grid, 256, smem>>>(msk);
    }

    // 3) Output projection: attn[65536,1024] @ Wo^T + bo
    {
        const int M = Bq * Ss * Hh;             // 65536
        dim3 grid(Ee / BNt, M / BMt);           // (8, 512)
        gemm_bf16x3<<<grid, 256, GEMM_SMEM>>>(ahi, alo, wohi, wolo, bo, out,
                                              M, Ee, Ee);
    }
}

// round 4
// speedup vs baseline: 3.5076x; 1.8409x over previous
#include <cuda_runtime.h>
#include <cuda_bf16.h>
#include <math_constants.h>
#include <cstdint>

// Problem constants
#define Bq 4
#define Ss 1024
#define Ee 1024
#define Hh 16
#define DKk 64

// ---------------------------------------------------------------------------
// Device scratch (no allocations allowed)
// ---------------------------------------------------------------------------
__device__ float g_Q[(size_t)Bq * Ss * Ee];            // 16 MiB (tf32-rounded)
__device__ float g_K[(size_t)Bq * Ss * Ee];            // 16 MiB (tf32-rounded)
__device__ float g_S[(size_t)Bq * Hh * Ss * Ss];       // 256 MiB raw scores [b][h][q][k]
__device__ float g_P[(size_t)Bq * Hh * Ss * Ss];       // 256 MiB probs [b][q][h][k], tf32-rounded
__device__ float g_xr[(size_t)Bq * Ss * Ee];           // 16 MiB x tf32-rounded
__device__ float g_Wqr[Ee * Ee], g_Wkr[Ee * Ee], g_Wor[Ee * Ee];

// ---------------------------------------------------------------------------
// PTX helpers (base compute_103 ISA only)
// ---------------------------------------------------------------------------
__device__ __forceinline__ uint32_t smem_u32(const void* p) {
    uint32_t a;
    asm("{ .reg .u64 t; cvta.to.shared.u64 t, %1; cvt.u32.u64 %0, t; }"
        : "=r"(a) : "l"(p));
    return a;
}
__device__ __forceinline__ void cp_async16(uint32_t saddr, const void* gaddr) {
    asm volatile("cp.async.cg.shared.global [%0], [%1], 16;"
                 :: "r"(saddr), "l"(gaddr) : "memory");
}
#define CP_COMMIT() asm volatile("cp.async.commit_group;" ::: "memory")
#define CP_WAIT(n)  asm volatile("cp.async.wait_group %0;" :: "n"(n) : "memory")

__device__ __forceinline__ void ldmat4(uint32_t& r0, uint32_t& r1,
                                       uint32_t& r2, uint32_t& r3, uint32_t addr) {
    asm volatile("ldmatrix.sync.aligned.m8n8.x4.shared.b16 {%0,%1,%2,%3}, [%4];"
                 : "=r"(r0), "=r"(r1), "=r"(r2), "=r"(r3) : "r"(addr));
}
__device__ __forceinline__ void mma1688_tf32(float* c, const uint32_t* a, const uint32_t* b) {
    asm volatile(
        "mma.sync.aligned.m16n8k8.row.col.f32.tf32.tf32.f32 "
        "{%0,%1,%2,%3}, {%4,%5,%6,%7}, {%8,%9}, {%0,%1,%2,%3};"
        : "+f"(c[0]), "+f"(c[1]), "+f"(c[2]), "+f"(c[3])
        : "r"(a[0]), "r"(a[1]), "r"(a[2]), "r"(a[3]), "r"(b[0]), "r"(b[1]));
}
__device__ __forceinline__ float rna_tf32(float x) {
    float r;
    asm("cvt.rna.tf32.f32 %0, %1;" : "=f"(r) : "f"(x));
    return r;
}

// ---------------------------------------------------------------------------
// TF32 GEMM-NT:  C[M,N] = A[M,K] @ B[N,K]^T (+ bias[N]),  batched via blockIdx.z
// 128x128 block tile, BK=32 (128B rows, 8x16B chunks, swizzle ch ^= row&7),
// 4-stage cp.async pipeline, 256 threads (8 warps 2x4, warp tile 64x32).
// ep_mode: 0 = +bias fp32 out, 1 = +bias + rna-tf32-rounded out, 2 = raw out.
// Batch offsets: A += (z/16)*sA_b + (z%16)*sA_h (same for B); C += z*sC_z.
// ---------------------------------------------------------------------------
#define BMt 128
#define BNt 128
#define BKt 32
#define NSTAGE 4
#define TILEB (128 * 128)              // one operand tile: 16 KiB
#define STAGE_BYTES (2 * TILEB)        // A + B: 32 KiB
#define GEMM_SMEM (NSTAGE * STAGE_BYTES)

__global__ __launch_bounds__(256, 1)
void gemm_tf32(const float* __restrict__ A, const float* __restrict__ B,
               const float* __restrict__ bias, float* __restrict__ C,
               int K, int lda, int ldb, int ldc,
               size_t sA_b, int sA_h, size_t sB_b, int sB_h, size_t sC_z,
               int ep_mode) {
    extern __shared__ char sm[];
    __shared__ float s_bias[BNt];

    const int tid  = threadIdx.x;
    const int lane = tid & 31;
    const int wid  = tid >> 5;
    const int warp_m = wid >> 2;   // 0..1
    const int warp_n = wid & 3;    // 0..3
    const int bm = blockIdx.y * BMt;
    const int bn = blockIdx.x * BNt;

    const int z = blockIdx.z;
    A += (size_t)(z >> 4) * sA_b + (size_t)(z & 15) * sA_h;
    B += (size_t)(z >> 4) * sB_b + (size_t)(z & 15) * sB_h;
    C += (size_t)z * sC_z;

    if (tid < BNt) s_bias[tid] = (ep_mode == 2) ? 0.0f : bias[bn + tid];

    const uint32_t smb = smem_u32(sm);

    auto load_stage = [&](int c) {
        const int k0 = c * BKt;
        const uint32_t stg = smb + (c % NSTAGE) * STAGE_BYTES;
#pragma unroll
        for (int t = 0; t < 8; ++t) {
            const int idx = t * 256 + tid;          // 0..2047
            const int region = idx >> 10;           // 0=A, 1=B
            const int w = idx & 1023;
            const int r = w >> 3, cc = w & 7;
            const uint32_t so = stg + region * TILEB + r * 128
                              + ((cc ^ (r & 7)) << 4);
            const float* src = region ? (B + (size_t)(bn + r) * ldb)
                                      : (A + (size_t)(bm + r) * lda);
            cp_async16(so, src + k0 + cc * 4);
        }
        CP_COMMIT();
    };

    const int nk = K / BKt;
    for (int c = 0; c < NSTAGE - 1; ++c) {
        if (c < nk) load_stage(c); else CP_COMMIT();
    }

    float acc[4][4][4];
#pragma unroll
    for (int mi = 0; mi < 4; ++mi)
#pragma unroll
        for (int ni = 0; ni < 4; ++ni)
#pragma unroll
            for (int j = 0; j < 4; ++j) acc[mi][ni][j] = 0.0f;

    const int tsub = (((lane >> 3) & 1) << 3) + (lane & 7);  // row-within-16 frag
    const int chof = lane >> 4;                               // k-chunk half select

    for (int c = 0; c < nk; ++c) {
        CP_WAIT(NSTAGE - 2);
        __syncthreads();
        if (c + NSTAGE - 1 < nk) load_stage(c + NSTAGE - 1);
        else CP_COMMIT();

        const uint32_t stgA = smb + (c % NSTAGE) * STAGE_BYTES;
        const uint32_t stgB = stgA + TILEB;
#pragma unroll
        for (int s = 0; s < 4; ++s) {
            uint32_t a[4][4], b[4][2];
#pragma unroll
            for (int mi = 0; mi < 4; ++mi) {
                const int row = warp_m * 64 + mi * 16 + tsub;
                const int ch = 2 * s + chof;
                ldmat4(a[mi][0], a[mi][1], a[mi][2], a[mi][3],
                       stgA + row * 128 + ((ch ^ (row & 7)) << 4));
            }
#pragma unroll
            for (int nf = 0; nf < 2; ++nf) {
                const int row = warp_n * 32 + nf * 16 + tsub;
                const int ch = 2 * s + chof;
                uint32_t q0, q1, q2, q3;
                ldmat4(q0, q1, q2, q3,
                       stgB + row * 128 + ((ch ^ (row & 7)) << 4));
                b[nf * 2 + 0][0] = q0; b[nf * 2 + 0][1] = q2;
                b[nf * 2 + 1][0] = q1; b[nf * 2 + 1][1] = q3;
            }
#pragma unroll
            for (int mi = 0; mi < 4; ++mi)
#pragma unroll
                for (int ni = 0; ni < 4; ++ni)
                    mma1688_tf32(acc[mi][ni], a[mi], b[ni]);
        }
    }

    // ---- epilogue ----
    const int r0 = lane >> 2;
    const int c0 = (lane & 3) * 2;
#pragma unroll
    for (int mi = 0; mi < 4; ++mi) {
        const int gr0 = bm + warp_m * 64 + mi * 16 + r0;
#pragma unroll
        for (int ni = 0; ni < 4; ++ni) {
            const int lc = warp_n * 32 + ni * 8 + c0;
            const int gc = bn + lc;
            float2 v0, v1;
            v0.x = acc[mi][ni][0] + s_bias[lc];
            v0.y = acc[mi][ni][1] + s_bias[lc + 1];
            v1.x = acc[mi][ni][2] + s_bias[lc];
            v1.y = acc[mi][ni][3] + s_bias[lc + 1];
            if (ep_mode == 1) {
                v0.x = rna_tf32(v0.x); v0.y = rna_tf32(v0.y);
                v1.x = rna_tf32(v1.x); v1.y = rna_tf32(v1.y);
            }
            *(float2*)&C[(size_t)gr0 * ldc + gc]       = v0;
            *(float2*)&C[(size_t)(gr0 + 8) * ldc + gc] = v1;
        }
    }
}

// ---------------------------------------------------------------------------
// fp32 -> tf32 (rna) pre-rounding, vectorized x4
// ---------------------------------------------------------------------------
__global__ void round_tf32_vec(const float4* __restrict__ src,
                               float4* __restrict__ dst, int n4) {
    int i = blockIdx.x * blockDim.x + threadIdx.x;
    if (i >= n4) return;
    float4 v = src[i];
    v.x = rna_tf32(v.x); v.y = rna_tf32(v.y);
    v.z = rna_tf32(v.z); v.w = rna_tf32(v.w);
    dst[i] = v;
}

// ---------------------------------------------------------------------------
// Mask + scale + softmax: g_S [b][h][q][:] -> g_P [b][q][h][:] (tf32-rounded)
// One warp per row; 256 threads = 8 rows per block.
// ---------------------------------------------------------------------------
__global__ __launch_bounds__(256)
void softmax_rows(const int* __restrict__ mask) {
    const int row  = blockIdx.x * 8 + (threadIdx.x >> 5);
    const int lane = threadIdx.x & 31;
    const int b = row >> 14;
    const int h = (row >> 10) & 15;
    const int q = row & 1023;

    const float4* src = (const float4*)(g_S + (size_t)row * Ss);
    const int4*   m4  = (const int4*)(mask + ((size_t)(b * Ss + q)) * Ss);

    float vals[32];
    float mx = -CUDART_INF_F;
#pragma unroll
    for (int j = 0; j < 8; ++j) {
        const float4 v = src[j * 32 + lane];
        const int4 mm  = m4[j * 32 + lane];
        const float s0 = mm.x ? v.x * 0.125f : -1e9f;
        const float s1 = mm.y ? v.y * 0.125f : -1e9f;
        const float s2 = mm.z ? v.z * 0.125f : -1e9f;
        const float s3 = mm.w ? v.w * 0.125f : -1e9f;
        vals[j * 4 + 0] = s0; vals[j * 4 + 1] = s1;
        vals[j * 4 + 2] = s2; vals[j * 4 + 3] = s3;
        mx = fmaxf(mx, fmaxf(fmaxf(s0, s1), fmaxf(s2, s3)));
    }
#pragma unroll
    for (int o = 16; o > 0; o >>= 1)
        mx = fmaxf(mx, __shfl_xor_sync(0xffffffffu, mx, o));

    float sum = 0.0f;
#pragma unroll
    for (int j = 0; j < 32; ++j) {
        vals[j] = __expf(vals[j] - mx);
        sum += vals[j];
    }
#pragma unroll
    for (int o = 16; o > 0; o >>= 1)
        sum += __shfl_xor_sync(0xffffffffu, sum, o);
    const float inv = 1.0f / sum;

    float4* dst = (float4*)(g_P + ((size_t)((b * Ss + q) * Hh + h)) * Ss);
#pragma unroll
    for (int j = 0; j < 8; ++j) {
        float4 o;
        o.x = rna_tf32(vals[j * 4 + 0] * inv);
        o.y = rna_tf32(vals[j * 4 + 1] * inv);
        o.z = rna_tf32(vals[j * 4 + 2] * inv);
        o.w = rna_tf32(vals[j * 4 + 3] * inv);
        dst[j * 32 + lane] = o;
    }
}

// ---------------------------------------------------------------------------
extern "C" void kernel_launch(void* const* d_in, const int* in_sizes, int n_in,
                              void* d_out, int out_size) {
    const float* x   = (const float*)d_in[0];
    const int*   msk = (const int*)  d_in[1];
    const float* Wq  = (const float*)d_in[2];
    const float* bq  = (const float*)d_in[3];
    const float* Wk  = (const float*)d_in[4];
    const float* bk  = (const float*)d_in[5];
    // d_in[6], d_in[7] = Wv, bv : unused (reference discards V)
    const float* Wo  = (const float*)d_in[8];
    const float* bo  = (const float*)d_in[9];
    float* out = (float*)d_out;

    float *qbuf, *kbuf, *sbuf, *pbuf, *xr, *wqr, *wkr, *wor;
    cudaGetSymbolAddress((void**)&qbuf, g_Q);
    cudaGetSymbolAddress((void**)&kbuf, g_K);
    cudaGetSymbolAddress((void**)&sbuf, g_S);
    cudaGetSymbolAddress((void**)&pbuf, g_P);
    cudaGetSymbolAddress((void**)&xr,  g_xr);
    cudaGetSymbolAddress((void**)&wqr, g_Wqr);
    cudaGetSymbolAddress((void**)&wkr, g_Wkr);
    cudaGetSymbolAddress((void**)&wor, g_Wor);

    cudaFuncSetAttribute(gemm_tf32,
                         cudaFuncAttributeMaxDynamicSharedMemorySize, GEMM_SMEM);

    // 0) tf32 rna pre-rounding (unbiased operands for all MMAs)
    {
        const int nx4 = Bq * Ss * Ee / 4;
        round_tf32_vec<<<(nx4 + 255) / 256, 256>>>((const float4*)x, (float4*)xr, nx4);
        const int nw4 = Ee * Ee / 4;
        round_tf32_vec<<<(nw4 + 255) / 256, 256>>>((const float4*)Wq, (float4*)wqr, nw4);
        round_tf32_vec<<<(nw4 + 255) / 256, 256>>>((const float4*)Wk, (float4*)wkr, nw4);
        round_tf32_vec<<<(nw4 + 255) / 256, 256>>>((const float4*)Wo, (float4*)wor, nw4);
    }

    // 1) Q, K projections: [4096,1024] @ W^T + b, output rna-rounded
    {
        dim3 grid(Ee / BNt, (Bq * Ss) / BMt, 1);   // (8, 32)
        gemm_tf32<<<grid, 256, GEMM_SMEM>>>(xr, wqr, bq, qbuf, Ee, Ee, Ee, Ee,
                                            0, 0, 0, 0, 0, 1);
        gemm_tf32<<<grid, 256, GEMM_SMEM>>>(xr, wkr, bk, kbuf, Ee, Ee, Ee, Ee,
                                            0, 0, 0, 0, 0, 1);
    }

    // 2) Scores: per (b,h) batched GEMM  S[bh] = Q[bh] @ K[bh]^T  (raw fp32)
    {
        dim3 grid(Ss / BNt, Ss / BMt, Bq * Hh);    // (8, 8, 64)
        gemm_tf32<<<grid, 256, GEMM_SMEM>>>(qbuf, kbuf, nullptr, sbuf,
                                            DKk, Ee, Ee, Ss,
                                            (size_t)Ss * Ee, DKk,
                                            (size_t)Ss * Ee, DKk,
                                            (size_t)Ss * Ss, 2);
    }

    // 3) Mask + softmax -> g_P (tf32-rounded probabilities)
    {
        softmax_rows<<<(Bq * Hh * Ss) / 8, 256>>>(msk);
    }

    // 4) Output projection: P[65536,1024] @ Wo^T + bo
    {
        const int M = Bq * Ss * Hh;                // 65536
        dim3 grid(Ee / BNt, M / BMt, 1);           // (8, 512)
        gemm_tf32<<<grid, 256, GEMM_SMEM>>>(pbuf, wor, bo, out, Ee, Ee, Ee, Ee,
                                            0, 0, 0, 0, 0, 0);
    }
}

// round 5
// speedup vs baseline: 3.8907x; 1.1092x over previous
#include <cuda_runtime.h>
#include <cuda_bf16.h>
#include <math_constants.h>
#include <cstdint>

// Problem constants
#define Bq 4
#define Ss 1024
#define Ee 1024
#define Hh 16
#define DKk 64

// ---------------------------------------------------------------------------
// Device scratch (no allocations allowed)
// ---------------------------------------------------------------------------
__device__ float g_Q[(size_t)Bq * Ss * Ee];            // 16 MiB (tf32-rounded)
__device__ float g_K[(size_t)Bq * Ss * Ee];            // 16 MiB (tf32-rounded)
__device__ float g_S[(size_t)Bq * Hh * Ss * Ss];       // 256 MiB raw scores [b][h][q][k]
__device__ float g_P[(size_t)Bq * Hh * Ss * Ss];       // 256 MiB probs [b][q][h][k], tf32-rounded
__device__ float g_xr[(size_t)Bq * Ss * Ee];           // 16 MiB x tf32-rounded
__device__ float g_Wqr[Ee * Ee], g_Wkr[Ee * Ee], g_Wor[Ee * Ee];

// ---------------------------------------------------------------------------
// PTX helpers (base compute_103 ISA only)
// ---------------------------------------------------------------------------
__device__ __forceinline__ uint32_t smem_u32(const void* p) {
    uint32_t a;
    asm("{ .reg .u64 t; cvta.to.shared.u64 t, %1; cvt.u32.u64 %0, t; }"
        : "=r"(a) : "l"(p));
    return a;
}
__device__ __forceinline__ void cp_async16(uint32_t saddr, const void* gaddr) {
    asm volatile("cp.async.cg.shared.global [%0], [%1], 16;"
                 :: "r"(saddr), "l"(gaddr) : "memory");
}
#define CP_COMMIT() asm volatile("cp.async.commit_group;" ::: "memory")
#define CP_WAIT(n)  asm volatile("cp.async.wait_group %0;" :: "n"(n) : "memory")

__device__ __forceinline__ void ldmat4(uint32_t& r0, uint32_t& r1,
                                       uint32_t& r2, uint32_t& r3, uint32_t addr) {
    asm volatile("ldmatrix.sync.aligned.m8n8.x4.shared.b16 {%0,%1,%2,%3}, [%4];"
                 : "=r"(r0), "=r"(r1), "=r"(r2), "=r"(r3) : "r"(addr));
}
__device__ __forceinline__ void mma1688_tf32(float* c, const uint32_t* a, const uint32_t* b) {
    asm volatile(
        "mma.sync.aligned.m16n8k8.row.col.f32.tf32.tf32.f32 "
        "{%0,%1,%2,%3}, {%4,%5,%6,%7}, {%8,%9}, {%0,%1,%2,%3};"
        : "+f"(c[0]), "+f"(c[1]), "+f"(c[2]), "+f"(c[3])
        : "r"(a[0]), "r"(a[1]), "r"(a[2]), "r"(a[3]), "r"(b[0]), "r"(b[1]));
}
__device__ __forceinline__ float rna_tf32(float x) {
    float r;
    asm("cvt.rna.tf32.f32 %0, %1;" : "=f"(r) : "f"(x));
    return r;
}

// ---------------------------------------------------------------------------
// TF32 GEMM-NT:  C[M,N] = A[M,K] @ B[N,K]^T (+ bias[N]),  batched via blockIdx.z
// 128x128 block tile, BK=32 (128B rows, 8x16B chunks, swizzle ch ^= row&7),
// 3-stage cp.async pipeline, 256 threads (8 warps 2x4, warp tile 64x32),
// 2 CTAs/SM for sync/epilogue overlap.
// ep_mode: 0 = +bias fp32 out, 1 = +bias + rna-tf32-rounded out, 2 = raw out.
// Batch offsets: A += (z/16)*sA_b + (z%16)*sA_h (same for B); C += z*sC_z.
// ---------------------------------------------------------------------------
#define BMt 128
#define BNt 128
#define BKt 32
#define NSTAGE 3
#define TILEB (128 * 128)              // one operand tile: 16 KiB
#define STAGE_BYTES (2 * TILEB)        // A + B: 32 KiB
#define GEMM_SMEM (NSTAGE * STAGE_BYTES)

__global__ __launch_bounds__(256, 2)
void gemm_tf32(const float* __restrict__ A, const float* __restrict__ B,
               const float* __restrict__ bias, float* __restrict__ C,
               int K, int lda, int ldb, int ldc,
               size_t sA_b, int sA_h, size_t sB_b, int sB_h, size_t sC_z,
               int ep_mode) {
    extern __shared__ char sm[];
    __shared__ float s_bias[BNt];

    const int tid  = threadIdx.x;
    const int lane = tid & 31;
    const int wid  = tid >> 5;
    const int warp_m = wid >> 2;   // 0..1
    const int warp_n = wid & 3;    // 0..3
    const int bm = blockIdx.y * BMt;
    const int bn = blockIdx.x * BNt;

    const int z = blockIdx.z;
    A += (size_t)(z >> 4) * sA_b + (size_t)(z & 15) * sA_h;
    B += (size_t)(z >> 4) * sB_b + (size_t)(z & 15) * sB_h;
    C += (size_t)z * sC_z;

    if (tid < BNt) s_bias[tid] = (ep_mode == 2) ? 0.0f : bias[bn + tid];

    const uint32_t smb = smem_u32(sm);

    auto load_stage = [&](int c) {
        const int k0 = c * BKt;
        const uint32_t stg = smb + (c % NSTAGE) * STAGE_BYTES;
#pragma unroll
        for (int t = 0; t < 8; ++t) {
            const int idx = t * 256 + tid;          // 0..2047
            const int region = idx >> 10;           // 0=A, 1=B
            const int w = idx & 1023;
            const int r = w >> 3, cc = w & 7;
            const uint32_t so = stg + region * TILEB + r * 128
                              + ((cc ^ (r & 7)) << 4);
            const float* src = region ? (B + (size_t)(bn + r) * ldb)
                                      : (A + (size_t)(bm + r) * lda);
            cp_async16(so, src + k0 + cc * 4);
        }
        CP_COMMIT();
    };

    const int nk = K / BKt;
    for (int c = 0; c < NSTAGE - 1; ++c) {
        if (c < nk) load_stage(c); else CP_COMMIT();
    }

    float acc[4][4][4];
#pragma unroll
    for (int mi = 0; mi < 4; ++mi)
#pragma unroll
        for (int ni = 0; ni < 4; ++ni)
#pragma unroll
            for (int j = 0; j < 4; ++j) acc[mi][ni][j] = 0.0f;

    const int tsub = (((lane >> 3) & 1) << 3) + (lane & 7);  // row-within-16 frag
    const int chof = lane >> 4;                               // k-chunk half select

    for (int c = 0; c < nk; ++c) {
        CP_WAIT(NSTAGE - 2);
        __syncthreads();
        if (c + NSTAGE - 1 < nk) load_stage(c + NSTAGE - 1);
        else CP_COMMIT();

        const uint32_t stgA = smb + (c % NSTAGE) * STAGE_BYTES;
        const uint32_t stgB = stgA + TILEB;
#pragma unroll
        for (int s = 0; s < 4; ++s) {
            uint32_t a[4][4], b[4][2];
#pragma unroll
            for (int mi = 0; mi < 4; ++mi) {
                const int row = warp_m * 64 + mi * 16 + tsub;
                const int ch = 2 * s + chof;
                ldmat4(a[mi][0], a[mi][1], a[mi][2], a[mi][3],
                       stgA + row * 128 + ((ch ^ (row & 7)) << 4));
            }
#pragma unroll
            for (int nf = 0; nf < 2; ++nf) {
                const int row = warp_n * 32 + nf * 16 + tsub;
                const int ch = 2 * s + chof;
                uint32_t q0, q1, q2, q3;
                ldmat4(q0, q1, q2, q3,
                       stgB + row * 128 + ((ch ^ (row & 7)) << 4));
                b[nf * 2 + 0][0] = q0; b[nf * 2 + 0][1] = q2;
                b[nf * 2 + 1][0] = q1; b[nf * 2 + 1][1] = q3;
            }
#pragma unroll
            for (int mi = 0; mi < 4; ++mi)
#pragma unroll
                for (int ni = 0; ni < 4; ++ni)
                    mma1688_tf32(acc[mi][ni], a[mi], b[ni]);
        }
    }

    // ---- epilogue ----
    const int r0 = lane >> 2;
    const int c0 = (lane & 3) * 2;
#pragma unroll
    for (int mi = 0; mi < 4; ++mi) {
        const int gr0 = bm + warp_m * 64 + mi * 16 + r0;
#pragma unroll
        for (int ni = 0; ni < 4; ++ni) {
            const int lc = warp_n * 32 + ni * 8 + c0;
            const int gc = bn + lc;
            float2 v0, v1;
            v0.x = acc[mi][ni][0] + s_bias[lc];
            v0.y = acc[mi][ni][1] + s_bias[lc + 1];
            v1.x = acc[mi][ni][2] + s_bias[lc];
            v1.y = acc[mi][ni][3] + s_bias[lc + 1];
            if (ep_mode == 1) {
                v0.x = rna_tf32(v0.x); v0.y = rna_tf32(v0.y);
                v1.x = rna_tf32(v1.x); v1.y = rna_tf32(v1.y);
            }
            *(float2*)&C[(size_t)gr0 * ldc + gc]       = v0;
            *(float2*)&C[(size_t)(gr0 + 8) * ldc + gc] = v1;
        }
    }
}

// ---------------------------------------------------------------------------
// fp32 -> tf32 (rna) pre-rounding, vectorized x4
// ---------------------------------------------------------------------------
__global__ void round_tf32_vec(const float4* __restrict__ src,
                               float4* __restrict__ dst, int n4) {
    int i = blockIdx.x * blockDim.x + threadIdx.x;
    if (i >= n4) return;
    float4 v = src[i];
    v.x = rna_tf32(v.x); v.y = rna_tf32(v.y);
    v.z = rna_tf32(v.z); v.w = rna_tf32(v.w);
    dst[i] = v;
}

// ---------------------------------------------------------------------------
// Mask + scale + softmax: g_S [b][h][q][:] -> g_P [b][q][h][:] (tf32-rounded)
// One warp per row; 256 threads = 8 rows per block.
// ---------------------------------------------------------------------------
__global__ __launch_bounds__(256)
void softmax_rows(const int* __restrict__ mask) {
    const int row  = blockIdx.x * 8 + (threadIdx.x >> 5);
    const int lane = threadIdx.x & 31;
    const int b = row >> 14;
    const int h = (row >> 10) & 15;
    const int q = row & 1023;

    const float4* src = (const float4*)(g_S + (size_t)row * Ss);
    const int4*   m4  = (const int4*)(mask + ((size_t)(b * Ss + q)) * Ss);

    float vals[32];
    float mx = -CUDART_INF_F;
#pragma unroll
    for (int j = 0; j < 8; ++j) {
        const float4 v = src[j * 32 + lane];
        const int4 mm  = m4[j * 32 + lane];
        const float s0 = mm.x ? v.x * 0.125f : -1e9f;
        const float s1 = mm.y ? v.y * 0.125f : -1e9f;
        const float s2 = mm.z ? v.z * 0.125f : -1e9f;
        const float s3 = mm.w ? v.w * 0.125f : -1e9f;
        vals[j * 4 + 0] = s0; vals[j * 4 + 1] = s1;
        vals[j * 4 + 2] = s2; vals[j * 4 + 3] = s3;
        mx = fmaxf(mx, fmaxf(fmaxf(s0, s1), fmaxf(s2, s3)));
    }
#pragma unroll
    for (int o = 16; o > 0; o >>= 1)
        mx = fmaxf(mx, __shfl_xor_sync(0xffffffffu, mx, o));

    float sum = 0.0f;
#pragma unroll
    for (int j = 0; j < 32; ++j) {
        vals[j] = __expf(vals[j] - mx);
        sum += vals[j];
    }
#pragma unroll
    for (int o = 16; o > 0; o >>= 1)
        sum += __shfl_xor_sync(0xffffffffu, sum, o);
    const float inv = 1.0f / sum;

    float4* dst = (float4*)(g_P + ((size_t)((b * Ss + q) * Hh + h)) * Ss);
#pragma unroll
    for (int j = 0; j < 8; ++j) {
        float4 o;
        o.x = rna_tf32(vals[j * 4 + 0] * inv);
        o.y = rna_tf32(vals[j * 4 + 1] * inv);
        o.z = rna_tf32(vals[j * 4 + 2] * inv);
        o.w = rna_tf32(vals[j * 4 + 3] * inv);
        dst[j * 32 + lane] = o;
    }
}

// ---------------------------------------------------------------------------
extern "C" void kernel_launch(void* const* d_in, const int* in_sizes, int n_in,
                              void* d_out, int out_size) {
    const float* x   = (const float*)d_in[0];
    const int*   msk = (const int*)  d_in[1];
    const float* Wq  = (const float*)d_in[2];
    const float* bq  = (const float*)d_in[3];
    const float* Wk  = (const float*)d_in[4];
    const float* bk  = (const float*)d_in[5];
    // d_in[6], d_in[7] = Wv, bv : unused (reference discards V)
    const float* Wo  = (const float*)d_in[8];
    const float* bo  = (const float*)d_in[9];
    float* out = (float*)d_out;

    float *qbuf, *kbuf, *sbuf, *pbuf, *xr, *wqr, *wkr, *wor;
    cudaGetSymbolAddress((void**)&qbuf, g_Q);
    cudaGetSymbolAddress((void**)&kbuf, g_K);
    cudaGetSymbolAddress((void**)&sbuf, g_S);
    cudaGetSymbolAddress((void**)&pbuf, g_P);
    cudaGetSymbolAddress((void**)&xr,  g_xr);
    cudaGetSymbolAddress((void**)&wqr, g_Wqr);
    cudaGetSymbolAddress((void**)&wkr, g_Wkr);
    cudaGetSymbolAddress((void**)&wor, g_Wor);

    cudaFuncSetAttribute(gemm_tf32,
                         cudaFuncAttributeMaxDynamicSharedMemorySize, GEMM_SMEM);

    // 0) tf32 rna pre-rounding (unbiased operands for all MMAs)
    {
        const int nx4 = Bq * Ss * Ee / 4;
        round_tf32_vec<<<(nx4 + 255) / 256, 256>>>((const float4*)x, (float4*)xr, nx4);
        const int nw4 = Ee * Ee / 4;
        round_tf32_vec<<<(nw4 + 255) / 256, 256>>>((const float4*)Wq, (float4*)wqr, nw4);
        round_tf32_vec<<<(nw4 + 255) / 256, 256>>>((const float4*)Wk, (float4*)wkr, nw4);
        round_tf32_vec<<<(nw4 + 255) / 256, 256>>>((const float4*)Wo, (float4*)wor, nw4);
    }

    // 1) Q, K projections: [4096,1024] @ W^T + b, output rna-rounded
    {
        dim3 grid(Ee / BNt, (Bq * Ss) / BMt, 1);   // (8, 32)
        gemm_tf32<<<grid, 256, GEMM_SMEM>>>(xr, wqr, bq, qbuf, Ee, Ee, Ee, Ee,
                                            0, 0, 0, 0, 0, 1);
        gemm_tf32<<<grid, 256, GEMM_SMEM>>>(xr, wkr, bk, kbuf, Ee, Ee, Ee, Ee,
                                            0, 0, 0, 0, 0, 1);
    }

    // 2) Scores: per (b,h) batched GEMM  S[bh] = Q[bh] @ K[bh]^T  (raw fp32)
    {
        dim3 grid(Ss / BNt, Ss / BMt, Bq * Hh);    // (8, 8, 64)
        gemm_tf32<<<grid, 256, GEMM_SMEM>>>(qbuf, kbuf, nullptr, sbuf,
                                            DKk, Ee, Ee, Ss,
                                            (size_t)Ss * Ee, DKk,
                                            (size_t)Ss * Ee, DKk,
                                            (size_t)Ss * Ss, 2);
    }

    // 3) Mask + softmax -> g_P (tf32-rounded probabilities)
    {
        softmax_rows<<<(Bq * Hh * Ss) / 8, 256>>>(msk);
    }

    // 4) Output projection: P[65536,1024] @ Wo^T + bo
    {
        const int M = Bq * Ss * Hh;                // 65536
        dim3 grid(Ee / BNt, M / BMt, 1);           // (8, 512)
        gemm_tf32<<<grid, 256, GEMM_SMEM>>>(pbuf, wor, bo, out, Ee, Ee, Ee, Ee,
                                            0, 0, 0, 0, 0, 0);
    }
}

// round 6
// speedup vs baseline: 4.1733x; 1.0726x over previous
#include <cuda_runtime.h>
#include <cuda_bf16.h>
#include <math_constants.h>
#include <cstdint>

// Problem constants
#define Bq 4
#define Ss 1024
#define Ee 1024
#define Hh 16
#define DKk 64

// ---------------------------------------------------------------------------
// Device scratch (no allocations allowed)
// ---------------------------------------------------------------------------
__device__ float g_Q[(size_t)Bq * Ss * Ee];            // 16 MiB (tf32-rounded)
__device__ float g_K[(size_t)Bq * Ss * Ee];            // 16 MiB (tf32-rounded)
__device__ float g_P[(size_t)Bq * Hh * Ss * Ss];       // 256 MiB probs [b][q][h][k], tf32-rounded
__device__ float g_xr[(size_t)Bq * Ss * Ee];           // 16 MiB x tf32-rounded
__device__ float g_Wqr[Ee * Ee], g_Wkr[Ee * Ee], g_Wor[Ee * Ee];

// ---------------------------------------------------------------------------
// PTX helpers (base compute_103 ISA only)
// ---------------------------------------------------------------------------
__device__ __forceinline__ uint32_t smem_u32(const void* p) {
    uint32_t a;
    asm("{ .reg .u64 t; cvta.to.shared.u64 t, %1; cvt.u32.u64 %0, t; }"
        : "=r"(a) : "l"(p));
    return a;
}
__device__ __forceinline__ void cp_async16(uint32_t saddr, const void* gaddr) {
    asm volatile("cp.async.cg.shared.global [%0], [%1], 16;"
                 :: "r"(saddr), "l"(gaddr) : "memory");
}
#define CP_COMMIT() asm volatile("cp.async.commit_group;" ::: "memory")
#define CP_WAIT(n)  asm volatile("cp.async.wait_group %0;" :: "n"(n) : "memory")

__device__ __forceinline__ void ldmat4(uint32_t& r0, uint32_t& r1,
                                       uint32_t& r2, uint32_t& r3, uint32_t addr) {
    asm volatile("ldmatrix.sync.aligned.m8n8.x4.shared.b16 {%0,%1,%2,%3}, [%4];"
                 : "=r"(r0), "=r"(r1), "=r"(r2), "=r"(r3) : "r"(addr));
}
__device__ __forceinline__ void mma1688_tf32(float* c, const uint32_t* a, const uint32_t* b) {
    asm volatile(
        "mma.sync.aligned.m16n8k8.row.col.f32.tf32.tf32.f32 "
        "{%0,%1,%2,%3}, {%4,%5,%6,%7}, {%8,%9}, {%0,%1,%2,%3};"
        : "+f"(c[0]), "+f"(c[1]), "+f"(c[2]), "+f"(c[3])
        : "r"(a[0]), "r"(a[1]), "r"(a[2]), "r"(a[3]), "r"(b[0]), "r"(b[1]));
}
__device__ __forceinline__ float rna_tf32(float x) {
    float r;
    asm("cvt.rna.tf32.f32 %0, %1;" : "=f"(r) : "f"(x));
    return r;
}

// ---------------------------------------------------------------------------
// TF32 GEMM-NT:  C[M,N] = A[M,K=1024] @ B[N,K]^T + bias[N]; all ld = 1024.
// 128x128 block tile, BK=32, 3-stage cp.async pipeline, 256 threads, 2 CTAs/SM.
// blockIdx.z == 1 switches to the (B2, bias2, C2) operand set (merged launches).
// ep_rna != 0: rna-tf32-round outputs.
// ---------------------------------------------------------------------------
#define BMt 128
#define BNt 128
#define BKt 32
#define NSTAGE 3
#define TILEB (128 * 128)              // one operand tile: 16 KiB
#define STAGE_BYTES (2 * TILEB)        // A + B: 32 KiB
#define GEMM_SMEM (NSTAGE * STAGE_BYTES)

__global__ __launch_bounds__(256, 2)
void gemm_tf32(const float* __restrict__ A, const float* __restrict__ B,
               const float* __restrict__ bias, float* __restrict__ C,
               const float* __restrict__ B2, const float* __restrict__ bias2,
               float* __restrict__ C2, int ep_rna) {
    extern __shared__ char sm[];
    __shared__ float s_bias[BNt];

    const int tid  = threadIdx.x;
    const int lane = tid & 31;
    const int wid  = tid >> 5;
    const int warp_m = wid >> 2;   // 0..1
    const int warp_n = wid & 3;    // 0..3
    const int bm = blockIdx.y * BMt;
    const int bn = blockIdx.x * BNt;

    if (blockIdx.z == 1) { B = B2; bias = bias2; C = C2; }

    if (tid < BNt) s_bias[tid] = bias[bn + tid];

    const uint32_t smb = smem_u32(sm);

    auto load_stage = [&](int c) {
        const int k0 = c * BKt;
        const uint32_t stg = smb + (c % NSTAGE) * STAGE_BYTES;
#pragma unroll
        for (int t = 0; t < 8; ++t) {
            const int idx = t * 256 + tid;          // 0..2047
            const int region = idx >> 10;           // 0=A, 1=B
            const int w = idx & 1023;
            const int r = w >> 3, cc = w & 7;
            const uint32_t so = stg + region * TILEB + r * 128
                              + ((cc ^ (r & 7)) << 4);
            const float* src = region ? (B + (size_t)(bn + r) * Ee)
                                      : (A + (size_t)(bm + r) * Ee);
            cp_async16(so, src + k0 + cc * 4);
        }
        CP_COMMIT();
    };

    const int nk = Ee / BKt;   // 32
    for (int c = 0; c < NSTAGE - 1; ++c) load_stage(c);

    float acc[4][4][4];
#pragma unroll
    for (int mi = 0; mi < 4; ++mi)
#pragma unroll
        for (int ni = 0; ni < 4; ++ni)
#pragma unroll
            for (int j = 0; j < 4; ++j) acc[mi][ni][j] = 0.0f;

    const int tsub = (((lane >> 3) & 1) << 3) + (lane & 7);
    const int chof = lane >> 4;

    for (int c = 0; c < nk; ++c) {
        CP_WAIT(NSTAGE - 2);
        __syncthreads();
        if (c + NSTAGE - 1 < nk) load_stage(c + NSTAGE - 1);
        else CP_COMMIT();

        const uint32_t stgA = smb + (c % NSTAGE) * STAGE_BYTES;
        const uint32_t stgB = stgA + TILEB;
#pragma unroll
        for (int s = 0; s < 4; ++s) {
            uint32_t a[4][4], b[4][2];
#pragma unroll
            for (int mi = 0; mi < 4; ++mi) {
                const int row = warp_m * 64 + mi * 16 + tsub;
                const int ch = 2 * s + chof;
                ldmat4(a[mi][0], a[mi][1], a[mi][2], a[mi][3],
                       stgA + row * 128 + ((ch ^ (row & 7)) << 4));
            }
#pragma unroll
            for (int nf = 0; nf < 2; ++nf) {
                const int row = warp_n * 32 + nf * 16 + tsub;
                const int ch = 2 * s + chof;
                uint32_t q0, q1, q2, q3;
                ldmat4(q0, q1, q2, q3,
                       stgB + row * 128 + ((ch ^ (row & 7)) << 4));
                b[nf * 2 + 0][0] = q0; b[nf * 2 + 0][1] = q2;
                b[nf * 2 + 1][0] = q1; b[nf * 2 + 1][1] = q3;
            }
#pragma unroll
            for (int mi = 0; mi < 4; ++mi)
#pragma unroll
                for (int ni = 0; ni < 4; ++ni)
                    mma1688_tf32(acc[mi][ni], a[mi], b[ni]);
        }
    }

    // ---- epilogue ----
    const int r0 = lane >> 2;
    const int c0 = (lane & 3) * 2;
#pragma unroll
    for (int mi = 0; mi < 4; ++mi) {
        const int gr0 = bm + warp_m * 64 + mi * 16 + r0;
#pragma unroll
        for (int ni = 0; ni < 4; ++ni) {
            const int lc = warp_n * 32 + ni * 8 + c0;
            const int gc = bn + lc;
            float2 v0, v1;
            v0.x = acc[mi][ni][0] + s_bias[lc];
            v0.y = acc[mi][ni][1] + s_bias[lc + 1];
            v1.x = acc[mi][ni][2] + s_bias[lc];
            v1.y = acc[mi][ni][3] + s_bias[lc + 1];
            if (ep_rna) {
                v0.x = rna_tf32(v0.x); v0.y = rna_tf32(v0.y);
                v1.x = rna_tf32(v1.x); v1.y = rna_tf32(v1.y);
            }
            *(float2*)&C[(size_t)gr0 * Ee + gc]       = v0;
            *(float2*)&C[(size_t)(gr0 + 8) * Ee + gc] = v1;
        }
    }
}

// ---------------------------------------------------------------------------
// Fused scores + mask + softmax: per CTA = one (b,h), 32 q-rows, full 1024 cols.
// Q strip in smem/regs (K=64 one-shot), K-matrix streamed in 128-row chunks
// (3-stage cp.async). Softmax entirely in registers + small smem reduce.
// Writes tf32-rounded probabilities to g_P [b][q][h][:].
// ---------------------------------------------------------------------------
#define FSM_A 0
#define FSM_B 8192
#define FUSED_SMEM (8192 + 3 * 32768)      // 106496

__global__ __launch_bounds__(256, 1)
void attn_fused(const int* __restrict__ mask) {
    extern __shared__ char sm[];
    __shared__ float s_red[32][4];

    const int tid  = threadIdx.x;
    const int lane = tid & 31;
    const int wid  = tid >> 5;
    const int warp_m = wid >> 2;   // 0..1 : 16 q-rows each
    const int warp_n = wid & 3;    // n interleave group
    const int b  = blockIdx.y >> 4;
    const int h  = blockIdx.y & 15;
    const int q0 = blockIdx.x * 32;

    const float* Ag = g_Q + ((size_t)(b * Ss + q0)) * Ee + h * DKk;
    const float* Bg = g_K + (size_t)b * Ss * Ee + h * DKk;

    const uint32_t smb = smem_u32(sm);
    const int tsub = (((lane >> 3) & 1) << 3) + (lane & 7);
    const int chof = lane >> 4;

    // ---- loaders ----
    {   // A: 32 rows x 64 floats -> 2 sub-tiles (k0-31, k32-63), 128B rows
#pragma unroll
        for (int t = 0; t < 2; ++t) {
            const int idx = t * 256 + tid;
            const int sub = idx >> 8, w = idx & 255;
            const int r = w >> 3, c = w & 7;
            cp_async16(smb + FSM_A + sub * 4096 + r * 128 + ((c ^ (r & 7)) << 4),
                       Ag + (size_t)r * Ee + sub * 32 + c * 4);
        }
    }
    auto loadB = [&](int ch) {
        const uint32_t stg = smb + FSM_B + (ch % 3) * 32768;
#pragma unroll
        for (int t = 0; t < 8; ++t) {
            const int idx = t * 256 + tid;
            const int sub = idx >> 10, w = idx & 1023;
            const int r = w >> 3, c = w & 7;
            cp_async16(stg + sub * 16384 + r * 128 + ((c ^ (r & 7)) << 4),
                       Bg + (size_t)(ch * 128 + r) * Ee + sub * 32 + c * 4);
        }
    };

    loadB(0); CP_COMMIT();      // group: A + B chunk 0
    loadB(1); CP_COMMIT();

    float acc[8][2][2][4];
#pragma unroll
    for (int ch = 0; ch < 8; ++ch)
#pragma unroll
        for (int t = 0; t < 2; ++t)
#pragma unroll
            for (int p = 0; p < 2; ++p)
#pragma unroll
                for (int j = 0; j < 4; ++j) acc[ch][t][p][j] = 0.0f;

    uint32_t afr[8][4];

#pragma unroll
    for (int ch = 0; ch < 8; ++ch) {
        CP_WAIT(1);
        __syncthreads();
        if (ch + 2 < 8) { loadB(ch + 2); CP_COMMIT(); } else CP_COMMIT();

        if (ch == 0) {
#pragma unroll
            for (int ks = 0; ks < 8; ++ks) {
                const int sub = ks >> 2, s = ks & 3;
                const int row = warp_m * 16 + tsub;
                const int cc = 2 * s + chof;
                ldmat4(afr[ks][0], afr[ks][1], afr[ks][2], afr[ks][3],
                       smb + FSM_A + sub * 4096 + row * 128 + ((cc ^ (row & 7)) << 4));
            }
        }

        const uint32_t stg = smb + FSM_B + (ch % 3) * 32768;
#pragma unroll
        for (int ks = 0; ks < 8; ++ks) {
            const int sub = ks >> 2, s = ks & 3;
            const int cc = 2 * s + chof;
#pragma unroll
            for (int t = 0; t < 2; ++t) {
                const int rowB = warp_n * 16 + t * 64 + tsub;
                uint32_t q0r, q1r, q2r, q3r;
                ldmat4(q0r, q1r, q2r, q3r,
                       stg + sub * 16384 + rowB * 128 + ((cc ^ (rowB & 7)) << 4));
                uint32_t be[2] = {q0r, q2r};
                uint32_t bo[2] = {q1r, q3r};
                mma1688_tf32(acc[ch][t][0], afr[ks], be);
                mma1688_tf32(acc[ch][t][1], afr[ks], bo);
            }
        }
    }

    // ---- mask + scale + softmax (rows r0 = warp_m*16 + lane/4, r1 = r0+8) ----
    const int r0 = warp_m * 16 + (lane >> 2);
    const int r1 = r0 + 8;
    const int ncol0 = warp_n * 16 + (lane & 3) * 2;
    const int* mrow0 = mask + ((size_t)(b * Ss + q0 + r0)) * Ss;
    const int* mrow1 = mask + ((size_t)(b * Ss + q0 + r1)) * Ss;

    float mx0 = -CUDART_INF_F, mx1 = -CUDART_INF_F;
#pragma unroll
    for (int ch = 0; ch < 8; ++ch)
#pragma unroll
        for (int t = 0; t < 2; ++t)
#pragma unroll
            for (int p = 0; p < 2; ++p) {
                const int n = ch * 128 + t * 64 + p * 8 + ncol0;
                const int2 m0 = *(const int2*)(mrow0 + n);
                const int2 m1 = *(const int2*)(mrow1 + n);
                float* v = acc[ch][t][p];
                v[0] = m0.x ? v[0] * 0.125f : -1e9f;
                v[1] = m0.y ? v[1] * 0.125f : -1e9f;
                v[2] = m1.x ? v[2] * 0.125f : -1e9f;
                v[3] = m1.y ? v[3] * 0.125f : -1e9f;
                mx0 = fmaxf(mx0, fmaxf(v[0], v[1]));
                mx1 = fmaxf(mx1, fmaxf(v[2], v[3]));
            }
    mx0 = fmaxf(mx0, __shfl_xor_sync(0xffffffffu, mx0, 1));
    mx0 = fmaxf(mx0, __shfl_xor_sync(0xffffffffu, mx0, 2));
    mx1 = fmaxf(mx1, __shfl_xor_sync(0xffffffffu, mx1, 1));
    mx1 = fmaxf(mx1, __shfl_xor_sync(0xffffffffu, mx1, 2));
    if ((lane & 3) == 0) { s_red[r0][warp_n] = mx0; s_red[r1][warp_n] = mx1; }
    __syncthreads();
    mx0 = fmaxf(fmaxf(s_red[r0][0], s_red[r0][1]), fmaxf(s_red[r0][2], s_red[r0][3]));
    mx1 = fmaxf(fmaxf(s_red[r1][0], s_red[r1][1]), fmaxf(s_red[r1][2], s_red[r1][3]));
    __syncthreads();

    float sum0 = 0.0f, sum1 = 0.0f;
#pragma unroll
    for (int ch = 0; ch < 8; ++ch)
#pragma unroll
        for (int t = 0; t < 2; ++t)
#pragma unroll
            for (int p = 0; p < 2; ++p) {
                float* v = acc[ch][t][p];
                v[0] = __expf(v[0] - mx0); v[1] = __expf(v[1] - mx0);
                v[2] = __expf(v[2] - mx1); v[3] = __expf(v[3] - mx1);
                sum0 += v[0] + v[1];
                sum1 += v[2] + v[3];
            }
    sum0 += __shfl_xor_sync(0xffffffffu, sum0, 1);
    sum0 += __shfl_xor_sync(0xffffffffu, sum0, 2);
    sum1 += __shfl_xor_sync(0xffffffffu, sum1, 1);
    sum1 += __shfl_xor_sync(0xffffffffu, sum1, 2);
    if ((lane & 3) == 0) { s_red[r0][warp_n] = sum0; s_red[r1][warp_n] = sum1; }
    __syncthreads();
    const float inv0 = 1.0f / (s_red[r0][0] + s_red[r0][1] + s_red[r0][2] + s_red[r0][3]);
    const float inv1 = 1.0f / (s_red[r1][0] + s_red[r1][1] + s_red[r1][2] + s_red[r1][3]);

    float* P0 = g_P + ((size_t)((b * Ss + q0 + r0) * Hh + h)) * Ss;
    float* P1 = g_P + ((size_t)((b * Ss + q0 + r1) * Hh + h)) * Ss;
#pragma unroll
    for (int ch = 0; ch < 8; ++ch)
#pragma unroll
        for (int t = 0; t < 2; ++t)
#pragma unroll
            for (int p = 0; p < 2; ++p) {
                const int n = ch * 128 + t * 64 + p * 8 + ncol0;
                const float* v = acc[ch][t][p];
                float2 o0, o1;
                o0.x = rna_tf32(v[0] * inv0); o0.y = rna_tf32(v[1] * inv0);
                o1.x = rna_tf32(v[2] * inv1); o1.y = rna_tf32(v[3] * inv1);
                *(float2*)(P0 + n) = o0;
                *(float2*)(P1 + n) = o1;
            }
}

// ---------------------------------------------------------------------------
// Merged fp32 -> tf32 (rna) pre-rounding: grid.y 0..3 = quarters of x, 4..6 = W's.
// Each segment = 262144 float4.
// ---------------------------------------------------------------------------
__global__ void round_tf32_all(const float4* __restrict__ x, float4* __restrict__ xr,
                               const float4* __restrict__ wq, float4* __restrict__ wqr,
                               const float4* __restrict__ wk, float4* __restrict__ wkr,
                               const float4* __restrict__ wo, float4* __restrict__ wor) {
    const int seg = blockIdx.y;
    const int i = blockIdx.x * blockDim.x + threadIdx.x;
    const float4* s; float4* d;
    if (seg < 4)      { s = x  + (size_t)seg * 262144; d = xr  + (size_t)seg * 262144; }
    else if (seg == 4){ s = wq; d = wqr; }
    else if (seg == 5){ s = wk; d = wkr; }
    else              { s = wo; d = wor; }
    float4 v = s[i];
    v.x = rna_tf32(v.x); v.y = rna_tf32(v.y);
    v.z = rna_tf32(v.z); v.w = rna_tf32(v.w);
    d[i] = v;
}

// ---------------------------------------------------------------------------
extern "C" void kernel_launch(void* const* d_in, const int* in_sizes, int n_in,
                              void* d_out, int out_size) {
    const float* x   = (const float*)d_in[0];
    const int*   msk = (const int*)  d_in[1];
    const float* Wq  = (const float*)d_in[2];
    const float* bq  = (const float*)d_in[3];
    const float* Wk  = (const float*)d_in[4];
    const float* bk  = (const float*)d_in[5];
    // d_in[6], d_in[7] = Wv, bv : unused (reference discards V)
    const float* Wo  = (const float*)d_in[8];
    const float* bo  = (const float*)d_in[9];
    float* out = (float*)d_out;

    float *qbuf, *kbuf, *pbuf, *xr, *wqr, *wkr, *wor;
    cudaGetSymbolAddress((void**)&qbuf, g_Q);
    cudaGetSymbolAddress((void**)&kbuf, g_K);
    cudaGetSymbolAddress((void**)&pbuf, g_P);
    cudaGetSymbolAddress((void**)&xr,  g_xr);
    cudaGetSymbolAddress((void**)&wqr, g_Wqr);
    cudaGetSymbolAddress((void**)&wkr, g_Wkr);
    cudaGetSymbolAddress((void**)&wor, g_Wor);

    cudaFuncSetAttribute(gemm_tf32,
                         cudaFuncAttributeMaxDynamicSharedMemorySize, GEMM_SMEM);
    cudaFuncSetAttribute(attn_fused,
                         cudaFuncAttributeMaxDynamicSharedMemorySize, FUSED_SMEM);

    // 0) tf32 rna pre-rounding (one launch)
    {
        dim3 grid(1024, 7);
        round_tf32_all<<<grid, 256>>>((const float4*)x,  (float4*)xr,
                                      (const float4*)Wq, (float4*)wqr,
                                      (const float4*)Wk, (float4*)wkr,
                                      (const float4*)Wo, (float4*)wor);
    }

    // 1) Q + K projections in ONE launch (z=0 -> Q set, z=1 -> K set), rna out
    {
        dim3 grid(Ee / BNt, (Bq * Ss) / BMt, 2);   // (8, 32, 2)
        gemm_tf32<<<grid, 256, GEMM_SMEM>>>(xr, wqr, bq, qbuf,
                                            wkr, bk, kbuf, 1);
    }

    // 2) Fused scores + mask + softmax -> g_P
    {
        dim3 grid(Ss / 32, Bq * Hh);               // (32, 64)
        attn_fused<<<grid, 256, FUSED_SMEM>>>(msk);
    }

    // 3) Output projection: P[65536,1024] @ Wo^T + bo
    {
        const int M = Bq * Ss * Hh;                // 65536
        dim3 grid(Ee / BNt, M / BMt, 1);           // (8, 512)
        gemm_tf32<<<grid, 256, GEMM_SMEM>>>(pbuf, wor, bo, out,
                                            wor, bo, out, 0);
    }
}

// round 7
// speedup vs baseline: 6.6093x; 1.5837x over previous
#include <cuda_runtime.h>
#include <cuda_fp16.h>
#include <math_constants.h>
#include <cstdint>

// Problem constants
#define Bq 4
#define Ss 1024
#define Ee 1024
#define Hh 16
#define DKk 64

// ---------------------------------------------------------------------------
// Device scratch (no allocations allowed)
// ---------------------------------------------------------------------------
__device__ __half g_Qh[(size_t)Bq * Ss * Ee];            // 8 MiB
__device__ __half g_Kh[(size_t)Bq * Ss * Ee];            // 8 MiB
__device__ __half g_Ph[(size_t)Bq * Hh * Ss * Ss];       // 128 MiB probs [b][q][h][k]
__device__ __half g_xh[(size_t)Bq * Ss * Ee];            // 8 MiB
__device__ __half g_Wqh[Ee * Ee], g_Wkh[Ee * Ee], g_Woh[Ee * Ee];

// ---------------------------------------------------------------------------
// PTX helpers (base compute_103 ISA only)
// ---------------------------------------------------------------------------
__device__ __forceinline__ uint32_t smem_u32(const void* p) {
    uint32_t a;
    asm("{ .reg .u64 t; cvta.to.shared.u64 t, %1; cvt.u32.u64 %0, t; }"
        : "=r"(a) : "l"(p));
    return a;
}
__device__ __forceinline__ void cp_async16(uint32_t saddr, const void* gaddr) {
    asm volatile("cp.async.cg.shared.global [%0], [%1], 16;"
                 :: "r"(saddr), "l"(gaddr) : "memory");
}
#define CP_COMMIT() asm volatile("cp.async.commit_group;" ::: "memory")
#define CP_WAIT(n)  asm volatile("cp.async.wait_group %0;" :: "n"(n) : "memory")

__device__ __forceinline__ void ldmat4(uint32_t& r0, uint32_t& r1,
                                       uint32_t& r2, uint32_t& r3, uint32_t addr) {
    asm volatile("ldmatrix.sync.aligned.m8n8.x4.shared.b16 {%0,%1,%2,%3}, [%4];"
                 : "=r"(r0), "=r"(r1), "=r"(r2), "=r"(r3) : "r"(addr));
}
__device__ __forceinline__ void mma_f16(float* c, const uint32_t* a, const uint32_t* b) {
    asm volatile(
        "mma.sync.aligned.m16n8k16.row.col.f32.f16.f16.f32 "
        "{%0,%1,%2,%3}, {%4,%5,%6,%7}, {%8,%9}, {%0,%1,%2,%3};"
        : "+f"(c[0]), "+f"(c[1]), "+f"(c[2]), "+f"(c[3])
        : "r"(a[0]), "r"(a[1]), "r"(a[2]), "r"(a[3]), "r"(b[0]), "r"(b[1]));
}

// ---------------------------------------------------------------------------
// FP16 GEMM-NT:  C[M,N] = A[M,K=1024] @ B[N,K]^T + bias[N]; all ld = 1024.
// 128x128 block tile, BK=32 (64B rows, 4x16B chunks, swizzle cc ^ (r>>1)&3),
// 4-stage cp.async pipeline, 256 threads (8 warps 2x4), 2 CTAs/SM.
// blockIdx.z == 1 switches to (B2, bias2, Ch2). half_out: 0 -> fp32 Cf, 1 -> half Ch.
// ---------------------------------------------------------------------------
#define BMt 128
#define BNt 128
#define BKt 32
#define NSTAGE 4
#define TILEB (128 * 64)               // one operand tile: 8 KiB
#define STAGE_BYTES (2 * TILEB)        // A + B: 16 KiB
#define GEMM_SMEM (NSTAGE * STAGE_BYTES)

__global__ __launch_bounds__(256, 2)
void gemm_f16(const __half* __restrict__ A, const __half* __restrict__ B,
              const float* __restrict__ bias, float* __restrict__ Cf,
              __half* __restrict__ Ch,
              const __half* __restrict__ B2, const float* __restrict__ bias2,
              __half* __restrict__ Ch2, int half_out) {
    extern __shared__ char sm[];
    __shared__ float s_bias[BNt];

    const int tid  = threadIdx.x;
    const int lane = tid & 31;
    const int wid  = tid >> 5;
    const int warp_m = wid >> 2;   // 0..1
    const int warp_n = wid & 3;    // 0..3
    const int bm = blockIdx.y * BMt;
    const int bn = blockIdx.x * BNt;

    if (blockIdx.z == 1) { B = B2; bias = bias2; Ch = Ch2; }

    if (tid < BNt) s_bias[tid] = bias[bn + tid];

    const uint32_t smb = smem_u32(sm);

    auto load_stage = [&](int c) {
        const int k0 = c * BKt;
        const uint32_t stg = smb + (c % NSTAGE) * STAGE_BYTES;
#pragma unroll
        for (int t = 0; t < 4; ++t) {
            const int idx = t * 256 + tid;          // 0..1023
            const int region = idx >> 9;            // 0=A, 1=B
            const int w = idx & 511;
            const int r = w >> 2, cc = w & 3;
            const uint32_t so = stg + region * TILEB + r * 64
                              + ((cc ^ ((r >> 1) & 3)) << 4);
            const __half* src = region ? (B + (size_t)(bn + r) * Ee)
                                       : (A + (size_t)(bm + r) * Ee);
            cp_async16(so, src + k0 + cc * 8);
        }
        CP_COMMIT();
    };

    const int nk = Ee / BKt;   // 32
    for (int c = 0; c < NSTAGE - 1; ++c) load_stage(c);

    float acc[4][4][4];
#pragma unroll
    for (int mi = 0; mi < 4; ++mi)
#pragma unroll
        for (int ni = 0; ni < 4; ++ni)
#pragma unroll
            for (int j = 0; j < 4; ++j) acc[mi][ni][j] = 0.0f;

    const int sub   = lane >> 3;                        // 0..3
    const int rlane = ((sub & 1) << 3) + (lane & 7);    // row within 16-row frag
    const int csub  = sub >> 1;                         // 16B chunk within k16

    for (int c = 0; c < nk; ++c) {
        CP_WAIT(NSTAGE - 2);
        __syncthreads();
        if (c + NSTAGE - 1 < nk) load_stage(c + NSTAGE - 1);
        else CP_COMMIT();

        const uint32_t stgA = smb + (c % NSTAGE) * STAGE_BYTES;
        const uint32_t stgB = stgA + TILEB;
#pragma unroll
        for (int ks = 0; ks < 2; ++ks) {
            const int chunk = ks * 2 + csub;
            uint32_t a[4][4], b[4][2];
#pragma unroll
            for (int mi = 0; mi < 4; ++mi) {
                const int row = warp_m * 64 + mi * 16 + rlane;
                ldmat4(a[mi][0], a[mi][1], a[mi][2], a[mi][3],
                       stgA + row * 64 + ((chunk ^ ((row >> 1) & 3)) << 4));
            }
#pragma unroll
            for (int nf = 0; nf < 2; ++nf) {
                const int row = warp_n * 32 + nf * 16 + rlane;
                uint32_t q0, q1, q2, q3;
                ldmat4(q0, q1, q2, q3,
                       stgB + row * 64 + ((chunk ^ ((row >> 1) & 3)) << 4));
                b[nf * 2 + 0][0] = q0; b[nf * 2 + 0][1] = q2;
                b[nf * 2 + 1][0] = q1; b[nf * 2 + 1][1] = q3;
            }
#pragma unroll
            for (int mi = 0; mi < 4; ++mi)
#pragma unroll
                for (int ni = 0; ni < 4; ++ni)
                    mma_f16(acc[mi][ni], a[mi], b[ni]);
        }
    }

    // ---- epilogue ----
    const int r0 = lane >> 2;
    const int c0 = (lane & 3) * 2;
#pragma unroll
    for (int mi = 0; mi < 4; ++mi) {
        const int gr0 = bm + warp_m * 64 + mi * 16 + r0;
#pragma unroll
        for (int ni = 0; ni < 4; ++ni) {
            const int lc = warp_n * 32 + ni * 8 + c0;
            const int gc = bn + lc;
            const float b0 = s_bias[lc], b1 = s_bias[lc + 1];
            if (half_out) {
                __half2 h0, h1;
                h0.x = __float2half_rn(acc[mi][ni][0] + b0);
                h0.y = __float2half_rn(acc[mi][ni][1] + b1);
                h1.x = __float2half_rn(acc[mi][ni][2] + b0);
                h1.y = __float2half_rn(acc[mi][ni][3] + b1);
                *(__half2*)&Ch[(size_t)gr0 * Ee + gc]       = h0;
                *(__half2*)&Ch[(size_t)(gr0 + 8) * Ee + gc] = h1;
            } else {
                float2 v0, v1;
                v0.x = acc[mi][ni][0] + b0; v0.y = acc[mi][ni][1] + b1;
                v1.x = acc[mi][ni][2] + b0; v1.y = acc[mi][ni][3] + b1;
                *(float2*)&Cf[(size_t)gr0 * Ee + gc]       = v0;
                *(float2*)&Cf[(size_t)(gr0 + 8) * Ee + gc] = v1;
            }
        }
    }
}

// ---------------------------------------------------------------------------
// Fused scores + mask + softmax: per CTA = one (b,h), 32 q-rows, full 1024 cols.
// Q strip (32x64 half, 128B rows) in smem one-shot; K streamed in 128-row
// chunks (16 KiB, 3-stage cp.async). Softmax in registers + smem reduce.
// Writes fp16 probabilities to g_Ph [b][q][h][:].
// ---------------------------------------------------------------------------
#define FSM_A 0
#define FSM_B 4096
#define KCH_B 16384
#define FUSED_SMEM (4096 + 3 * KCH_B)      // 53248

__global__ __launch_bounds__(256, 1)
void attn_fused(const int* __restrict__ mask) {
    extern __shared__ char sm[];
    __shared__ float s_red[32][4];

    const int tid  = threadIdx.x;
    const int lane = tid & 31;
    const int wid  = tid >> 5;
    const int warp_m = wid >> 2;   // 0..1 : 16 q-rows each
    const int warp_n = wid & 3;    // n interleave group
    const int b  = blockIdx.y >> 4;
    const int h  = blockIdx.y & 15;
    const int q0 = blockIdx.x * 32;

    const __half* Ag = g_Qh + ((size_t)(b * Ss + q0)) * Ee + h * DKk;
    const __half* Bg = g_Kh + (size_t)b * Ss * Ee + h * DKk;

    const uint32_t smb = smem_u32(sm);
    const int tsub = (((lane >> 3) & 1) << 3) + (lane & 7);
    const int chof = lane >> 4;      // 16B chunk within k16 pair

    // ---- loaders (rows = 64 halves = 128B = 8 x 16B chunks, swizzle c^(r&7)) ----
    {   // A: 32 rows -> 256 transfers, 1 iter
        const int r = tid >> 3, c = tid & 7;
        cp_async16(smb + FSM_A + r * 128 + ((c ^ (r & 7)) << 4),
                   Ag + (size_t)r * Ee + c * 8);
    }
    auto loadB = [&](int ch) {
        const uint32_t stg = smb + FSM_B + (ch % 3) * KCH_B;
#pragma unroll
        for (int t = 0; t < 4; ++t) {
            const int idx = t * 256 + tid;
            const int r = idx >> 3, c = idx & 7;
            cp_async16(stg + r * 128 + ((c ^ (r & 7)) << 4),
                       Bg + (size_t)(ch * 128 + r) * Ee + c * 8);
        }
    };

    loadB(0); CP_COMMIT();      // group: A + B chunk 0
    loadB(1); CP_COMMIT();

    float acc[8][2][2][4];
#pragma unroll
    for (int ch = 0; ch < 8; ++ch)
#pragma unroll
        for (int t = 0; t < 2; ++t)
#pragma unroll
            for (int p = 0; p < 2; ++p)
#pragma unroll
                for (int j = 0; j < 4; ++j) acc[ch][t][p][j] = 0.0f;

    uint32_t afr[4][4];

#pragma unroll
    for (int ch = 0; ch < 8; ++ch) {
        CP_WAIT(1);
        __syncthreads();
        if (ch + 2 < 8) { loadB(ch + 2); CP_COMMIT(); } else CP_COMMIT();

        if (ch == 0) {
#pragma unroll
            for (int s = 0; s < 4; ++s) {
                const int row = warp_m * 16 + tsub;
                const int cc = 2 * s + chof;
                ldmat4(afr[s][0], afr[s][1], afr[s][2], afr[s][3],
                       smb + FSM_A + row * 128 + ((cc ^ (row & 7)) << 4));
            }
        }

        const uint32_t stg = smb + FSM_B + (ch % 3) * KCH_B;
#pragma unroll
        for (int s = 0; s < 4; ++s) {
            const int cc = 2 * s + chof;
#pragma unroll
            for (int t = 0; t < 2; ++t) {
                const int rowB = warp_n * 16 + t * 64 + tsub;
                uint32_t q0r, q1r, q2r, q3r;
                ldmat4(q0r, q1r, q2r, q3r,
                       stg + rowB * 128 + ((cc ^ (rowB & 7)) << 4));
                uint32_t be[2] = {q0r, q2r};
                uint32_t bo[2] = {q1r, q3r};
                mma_f16(acc[ch][t][0], afr[s], be);
                mma_f16(acc[ch][t][1], afr[s], bo);
            }
        }
    }

    // ---- mask + scale + softmax ----
    const int r0 = warp_m * 16 + (lane >> 2);
    const int r1 = r0 + 8;
    const int ncol0 = warp_n * 16 + (lane & 3) * 2;
    const int* mrow0 = mask + ((size_t)(b * Ss + q0 + r0)) * Ss;
    const int* mrow1 = mask + ((size_t)(b * Ss + q0 + r1)) * Ss;

    float mx0 = -CUDART_INF_F, mx1 = -CUDART_INF_F;
#pragma unroll
    for (int ch = 0; ch < 8; ++ch)
#pragma unroll
        for (int t = 0; t < 2; ++t)
#pragma unroll
            for (int p = 0; p < 2; ++p) {
                const int n = ch * 128 + t * 64 + p * 8 + ncol0;
                const int2 m0 = *(const int2*)(mrow0 + n);
                const int2 m1 = *(const int2*)(mrow1 + n);
                float* v = acc[ch][t][p];
                v[0] = m0.x ? v[0] * 0.125f : -1e9f;
                v[1] = m0.y ? v[1] * 0.125f : -1e9f;
                v[2] = m1.x ? v[2] * 0.125f : -1e9f;
                v[3] = m1.y ? v[3] * 0.125f : -1e9f;
                mx0 = fmaxf(mx0, fmaxf(v[0], v[1]));
                mx1 = fmaxf(mx1, fmaxf(v[2], v[3]));
            }
    mx0 = fmaxf(mx0, __shfl_xor_sync(0xffffffffu, mx0, 1));
    mx0 = fmaxf(mx0, __shfl_xor_sync(0xffffffffu, mx0, 2));
    mx1 = fmaxf(mx1, __shfl_xor_sync(0xffffffffu, mx1, 1));
    mx1 = fmaxf(mx1, __shfl_xor_sync(0xffffffffu, mx1, 2));
    if ((lane & 3) == 0) { s_red[r0][warp_n] = mx0; s_red[r1][warp_n] = mx1; }
    __syncthreads();
    mx0 = fmaxf(fmaxf(s_red[r0][0], s_red[r0][1]), fmaxf(s_red[r0][2], s_red[r0][3]));
    mx1 = fmaxf(fmaxf(s_red[r1][0], s_red[r1][1]), fmaxf(s_red[r1][2], s_red[r1][3]));
    __syncthreads();

    float sum0 = 0.0f, sum1 = 0.0f;
#pragma unroll
    for (int ch = 0; ch < 8; ++ch)
#pragma unroll
        for (int t = 0; t < 2; ++t)
#pragma unroll
            for (int p = 0; p < 2; ++p) {
                float* v = acc[ch][t][p];
                v[0] = __expf(v[0] - mx0); v[1] = __expf(v[1] - mx0);
                v[2] = __expf(v[2] - mx1); v[3] = __expf(v[3] - mx1);
                sum0 += v[0] + v[1];
                sum1 += v[2] + v[3];
            }
    sum0 += __shfl_xor_sync(0xffffffffu, sum0, 1);
    sum0 += __shfl_xor_sync(0xffffffffu, sum0, 2);
    sum1 += __shfl_xor_sync(0xffffffffu, sum1, 1);
    sum1 += __shfl_xor_sync(0xffffffffu, sum1, 2);
    if ((lane & 3) == 0) { s_red[r0][warp_n] = sum0; s_red[r1][warp_n] = sum1; }
    __syncthreads();
    const float inv0 = 1.0f / (s_red[r0][0] + s_red[r0][1] + s_red[r0][2] + s_red[r0][3]);
    const float inv1 = 1.0f / (s_red[r1][0] + s_red[r1][1] + s_red[r1][2] + s_red[r1][3]);

    __half* P0 = g_Ph + ((size_t)((b * Ss + q0 + r0) * Hh + h)) * Ss;
    __half* P1 = g_Ph + ((size_t)((b * Ss + q0 + r1) * Hh + h)) * Ss;
#pragma unroll
    for (int ch = 0; ch < 8; ++ch)
#pragma unroll
        for (int t = 0; t < 2; ++t)
#pragma unroll
            for (int p = 0; p < 2; ++p) {
                const int n = ch * 128 + t * 64 + p * 8 + ncol0;
                const float* v = acc[ch][t][p];
                __half2 o0, o1;
                o0.x = __float2half_rn(v[0] * inv0); o0.y = __float2half_rn(v[1] * inv0);
                o1.x = __float2half_rn(v[2] * inv1); o1.y = __float2half_rn(v[3] * inv1);
                *(__half2*)(P0 + n) = o0;
                *(__half2*)(P1 + n) = o1;
            }
}

// ---------------------------------------------------------------------------
// Merged fp32 -> fp16 (rn) conversion: grid.y 0..3 = quarters of x, 4..6 = W's.
// Each segment = 262144 float4 -> 262144 half4.
// ---------------------------------------------------------------------------
__global__ void conv_f16_all(const float4* __restrict__ x, __half2* __restrict__ xh,
                             const float4* __restrict__ wq, __half2* __restrict__ wqh,
                             const float4* __restrict__ wk, __half2* __restrict__ wkh,
                             const float4* __restrict__ wo, __half2* __restrict__ woh) {
    const int seg = blockIdx.y;
    const int i = blockIdx.x * blockDim.x + threadIdx.x;
    const float4* s; __half2* d;
    if (seg < 4)      { s = x  + (size_t)seg * 262144; d = xh  + (size_t)seg * 524288; }
    else if (seg == 4){ s = wq; d = wqh; }
    else if (seg == 5){ s = wk; d = wkh; }
    else              { s = wo; d = woh; }
    const float4 v = s[i];
    __half2 h0, h1;
    h0.x = __float2half_rn(v.x); h0.y = __float2half_rn(v.y);
    h1.x = __float2half_rn(v.z); h1.y = __float2half_rn(v.w);
    d[i * 2 + 0] = h0;
    d[i * 2 + 1] = h1;
}

// ---------------------------------------------------------------------------
extern "C" void kernel_launch(void* const* d_in, const int* in_sizes, int n_in,
                              void* d_out, int out_size) {
    const float* x   = (const float*)d_in[0];
    const int*   msk = (const int*)  d_in[1];
    const float* Wq  = (const float*)d_in[2];
    const float* bq  = (const float*)d_in[3];
    const float* Wk  = (const float*)d_in[4];
    const float* bk  = (const float*)d_in[5];
    // d_in[6], d_in[7] = Wv, bv : unused (reference discards V)
    const float* Wo  = (const float*)d_in[8];
    const float* bo  = (const float*)d_in[9];
    float* out = (float*)d_out;

    __half *qh, *kh, *ph, *xh, *wqh, *wkh, *woh;
    cudaGetSymbolAddress((void**)&qh,  g_Qh);
    cudaGetSymbolAddress((void**)&kh,  g_Kh);
    cudaGetSymbolAddress((void**)&ph,  g_Ph);
    cudaGetSymbolAddress((void**)&xh,  g_xh);
    cudaGetSymbolAddress((void**)&wqh, g_Wqh);
    cudaGetSymbolAddress((void**)&wkh, g_Wkh);
    cudaGetSymbolAddress((void**)&woh, g_Woh);

    cudaFuncSetAttribute(gemm_f16,
                         cudaFuncAttributeMaxDynamicSharedMemorySize, GEMM_SMEM);
    cudaFuncSetAttribute(attn_fused,
                         cudaFuncAttributeMaxDynamicSharedMemorySize, FUSED_SMEM);

    // 0) fp32 -> fp16 conversion (one launch)
    {
        dim3 grid(1024, 7);
        conv_f16_all<<<grid, 256>>>((const float4*)x,  (__half2*)xh,
                                    (const float4*)Wq, (__half2*)wqh,
                                    (const float4*)Wk, (__half2*)wkh,
                                    (const float4*)Wo, (__half2*)woh);
    }

    // 1) Q + K projections in ONE launch (z=0 -> Q, z=1 -> K), fp16 outputs
    {
        dim3 grid(Ee / BNt, (Bq * Ss) / BMt, 2);   // (8, 32, 2)
        gemm_f16<<<grid, 256, GEMM_SMEM>>>(xh, wqh, bq, nullptr, qh,
                                           wkh, bk, kh, 1);
    }

    // 2) Fused scores + mask + softmax -> g_Ph (fp16)
    {
        dim3 grid(Ss / 32, Bq * Hh);               // (32, 64)
        attn_fused<<<grid, 256, FUSED_SMEM>>>(msk);
    }

    // 3) Output projection: P[65536,1024] @ Wo^T + bo -> fp32 out
    {
        const int M = Bq * Ss * Hh;                // 65536
        dim3 grid(Ee / BNt, M / BMt, 1);           // (8, 512)
        gemm_f16<<<grid, 256, GEMM_SMEM>>>(ph, woh, bo, out, nullptr,
                                           woh, bo, nullptr, 0);
    }
}

// round 8
// speedup vs baseline: 7.1460x; 1.0812x over previous
#include <cuda_runtime.h>
#include <cuda_fp16.h>
#include <math_constants.h>
#include <cstdint>

// Problem constants
#define Bq 4
#define Ss 1024
#define Ee 1024
#define Hh 16
#define DKk 64

// ---------------------------------------------------------------------------
// Device scratch (no allocations allowed)
// ---------------------------------------------------------------------------
__device__ __half g_Qh[(size_t)Bq * Ss * Ee];            // 8 MiB
__device__ __half g_Kh[(size_t)Bq * Ss * Ee];            // 8 MiB
__device__ __half g_Ph[(size_t)Bq * Hh * Ss * Ss];       // 128 MiB probs [b][q][h][k]
__device__ __half g_xh[(size_t)Bq * Ss * Ee];            // 8 MiB
__device__ __half g_Wqh[Ee * Ee], g_Wkh[Ee * Ee], g_Woh[Ee * Ee];

// ---------------------------------------------------------------------------
// PTX helpers (base compute_103 ISA only)
// ---------------------------------------------------------------------------
__device__ __forceinline__ uint32_t smem_u32(const void* p) {
    uint32_t a;
    asm("{ .reg .u64 t; cvta.to.shared.u64 t, %1; cvt.u32.u64 %0, t; }"
        : "=r"(a) : "l"(p));
    return a;
}
__device__ __forceinline__ void cp_async16(uint32_t saddr, const void* gaddr) {
    asm volatile("cp.async.cg.shared.global [%0], [%1], 16;"
                 :: "r"(saddr), "l"(gaddr) : "memory");
}
#define CP_COMMIT() asm volatile("cp.async.commit_group;" ::: "memory")
#define CP_WAIT(n)  asm volatile("cp.async.wait_group %0;" :: "n"(n) : "memory")

__device__ __forceinline__ void ldmat4(uint32_t& r0, uint32_t& r1,
                                       uint32_t& r2, uint32_t& r3, uint32_t addr) {
    asm volatile("ldmatrix.sync.aligned.m8n8.x4.shared.b16 {%0,%1,%2,%3}, [%4];"
                 : "=r"(r0), "=r"(r1), "=r"(r2), "=r"(r3) : "r"(addr));
}
__device__ __forceinline__ void mma_f16(float* c, const uint32_t* a, const uint32_t* b) {
    asm volatile(
        "mma.sync.aligned.m16n8k16.row.col.f32.f16.f16.f32 "
        "{%0,%1,%2,%3}, {%4,%5,%6,%7}, {%8,%9}, {%0,%1,%2,%3};"
        : "+f"(c[0]), "+f"(c[1]), "+f"(c[2]), "+f"(c[3])
        : "r"(a[0]), "r"(a[1]), "r"(a[2]), "r"(a[3]), "r"(b[0]), "r"(b[1]));
}

// ---------------------------------------------------------------------------
// FP16 GEMM-NT:  C[M,N] = A[M,K=1024] @ B[N,K]^T + bias[N]; all ld = 1024.
// 128x128 block tile, BK=64 (128B rows, 8x16B chunks, swizzle cc ^ (r&7)),
// 3-stage cp.async pipeline (16 chunks -> 16 syncs), 256 threads, 2 CTAs/SM.
// blockIdx.z == 1 switches to (B2, bias2, Ch2). half_out: 0 -> fp32 Cf, 1 -> half Ch.
// ---------------------------------------------------------------------------
#define BMt 128
#define BNt 128
#define BKt 64
#define NSTAGE 3
#define TILEB (128 * 128)              // one operand tile: 16 KiB
#define STAGE_BYTES (2 * TILEB)        // A + B: 32 KiB
#define GEMM_SMEM (NSTAGE * STAGE_BYTES)

__global__ __launch_bounds__(256, 2)
void gemm_f16(const __half* __restrict__ A, const __half* __restrict__ B,
              const float* __restrict__ bias, float* __restrict__ Cf,
              __half* __restrict__ Ch,
              const __half* __restrict__ B2, const float* __restrict__ bias2,
              __half* __restrict__ Ch2, int half_out) {
    extern __shared__ char sm[];
    __shared__ float s_bias[BNt];

    const int tid  = threadIdx.x;
    const int lane = tid & 31;
    const int wid  = tid >> 5;
    const int warp_m = wid >> 2;   // 0..1
    const int warp_n = wid & 3;    // 0..3
    const int bm = blockIdx.y * BMt;
    const int bn = blockIdx.x * BNt;

    if (blockIdx.z == 1) { B = B2; bias = bias2; Ch = Ch2; }

    if (tid < BNt) s_bias[tid] = bias[bn + tid];

    const uint32_t smb = smem_u32(sm);

    auto load_stage = [&](int c) {
        const int k0 = c * BKt;
        const uint32_t stg = smb + (c % NSTAGE) * STAGE_BYTES;
#pragma unroll
        for (int t = 0; t < 8; ++t) {
            const int idx = t * 256 + tid;          // 0..2047
            const int region = idx >> 10;           // 0=A, 1=B
            const int w = idx & 1023;
            const int r = w >> 3, cc = w & 7;
            const uint32_t so = stg + region * TILEB + r * 128
                              + ((cc ^ (r & 7)) << 4);
            const __half* src = region ? (B + (size_t)(bn + r) * Ee)
                                       : (A + (size_t)(bm + r) * Ee);
            cp_async16(so, src + k0 + cc * 8);
        }
        CP_COMMIT();
    };

    const int nk = Ee / BKt;   // 16
    for (int c = 0; c < NSTAGE - 1; ++c) load_stage(c);

    float acc[4][4][4];
#pragma unroll
    for (int mi = 0; mi < 4; ++mi)
#pragma unroll
        for (int ni = 0; ni < 4; ++ni)
#pragma unroll
            for (int j = 0; j < 4; ++j) acc[mi][ni][j] = 0.0f;

    const int tsub = (((lane >> 3) & 1) << 3) + (lane & 7);  // row within 16-row frag
    const int chof = lane >> 4;                               // 16B chunk within k16

    for (int c = 0; c < nk; ++c) {
        CP_WAIT(NSTAGE - 2);
        __syncthreads();
        if (c + NSTAGE - 1 < nk) load_stage(c + NSTAGE - 1);
        else CP_COMMIT();

        const uint32_t stgA = smb + (c % NSTAGE) * STAGE_BYTES;
        const uint32_t stgB = stgA + TILEB;
#pragma unroll
        for (int ks = 0; ks < 4; ++ks) {
            const int chunk = 2 * ks + chof;
            uint32_t a[4][4], b[4][2];
#pragma unroll
            for (int mi = 0; mi < 4; ++mi) {
                const int row = warp_m * 64 + mi * 16 + tsub;
                ldmat4(a[mi][0], a[mi][1], a[mi][2], a[mi][3],
                       stgA + row * 128 + ((chunk ^ (row & 7)) << 4));
            }
#pragma unroll
            for (int nf = 0; nf < 2; ++nf) {
                const int row = warp_n * 32 + nf * 16 + tsub;
                uint32_t q0, q1, q2, q3;
                ldmat4(q0, q1, q2, q3,
                       stgB + row * 128 + ((chunk ^ (row & 7)) << 4));
                b[nf * 2 + 0][0] = q0; b[nf * 2 + 0][1] = q2;
                b[nf * 2 + 1][0] = q1; b[nf * 2 + 1][1] = q3;
            }
#pragma unroll
            for (int mi = 0; mi < 4; ++mi)
#pragma unroll
                for (int ni = 0; ni < 4; ++ni)
                    mma_f16(acc[mi][ni], a[mi], b[ni]);
        }
    }

    // ---- epilogue ----
    const int r0 = lane >> 2;
    const int c0 = (lane & 3) * 2;
#pragma unroll
    for (int mi = 0; mi < 4; ++mi) {
        const int gr0 = bm + warp_m * 64 + mi * 16 + r0;
#pragma unroll
        for (int ni = 0; ni < 4; ++ni) {
            const int lc = warp_n * 32 + ni * 8 + c0;
            const int gc = bn + lc;
            const float b0 = s_bias[lc], b1 = s_bias[lc + 1];
            if (half_out) {
                __half2 h0, h1;
                h0.x = __float2half_rn(acc[mi][ni][0] + b0);
                h0.y = __float2half_rn(acc[mi][ni][1] + b1);
                h1.x = __float2half_rn(acc[mi][ni][2] + b0);
                h1.y = __float2half_rn(acc[mi][ni][3] + b1);
                *(__half2*)&Ch[(size_t)gr0 * Ee + gc]       = h0;
                *(__half2*)&Ch[(size_t)(gr0 + 8) * Ee + gc] = h1;
            } else {
                float2 v0, v1;
                v0.x = acc[mi][ni][0] + b0; v0.y = acc[mi][ni][1] + b1;
                v1.x = acc[mi][ni][2] + b0; v1.y = acc[mi][ni][3] + b1;
                *(float2*)&Cf[(size_t)gr0 * Ee + gc]       = v0;
                *(float2*)&Cf[(size_t)(gr0 + 8) * Ee + gc] = v1;
            }
        }
    }
}

// ---------------------------------------------------------------------------
// Fused scores + mask + softmax: per CTA = one (b,h), 32 q-rows, full 1024 cols.
// Q strip (32x64 half, 128B rows) in smem one-shot; K streamed in 128-row
// chunks (16 KiB, 3-stage cp.async). Softmax in registers + smem reduce.
// Writes fp16 probabilities to g_Ph [b][q][h][:].
// ---------------------------------------------------------------------------
#define FSM_A 0
#define FSM_B 4096
#define KCH_B 16384
#define FUSED_SMEM (4096 + 3 * KCH_B)      // 53248

__global__ __launch_bounds__(256, 1)
void attn_fused(const int* __restrict__ mask) {
    extern __shared__ char sm[];
    __shared__ float s_red[32][4];

    const int tid  = threadIdx.x;
    const int lane = tid & 31;
    const int wid  = tid >> 5;
    const int warp_m = wid >> 2;   // 0..1 : 16 q-rows each
    const int warp_n = wid & 3;    // n interleave group
    const int b  = blockIdx.y >> 4;
    const int h  = blockIdx.y & 15;
    const int q0 = blockIdx.x * 32;

    const __half* Ag = g_Qh + ((size_t)(b * Ss + q0)) * Ee + h * DKk;
    const __half* Bg = g_Kh + (size_t)b * Ss * Ee + h * DKk;

    const uint32_t smb = smem_u32(sm);
    const int tsub = (((lane >> 3) & 1) << 3) + (lane & 7);
    const int chof = lane >> 4;      // 16B chunk within k16 pair

    // ---- loaders (rows = 64 halves = 128B = 8 x 16B chunks, swizzle c^(r&7)) ----
    {   // A: 32 rows -> 256 transfers, 1 iter
        const int r = tid >> 3, c = tid & 7;
        cp_async16(smb + FSM_A + r * 128 + ((c ^ (r & 7)) << 4),
                   Ag + (size_t)r * Ee + c * 8);
    }
    auto loadB = [&](int ch) {
        const uint32_t stg = smb + FSM_B + (ch % 3) * KCH_B;
#pragma unroll
        for (int t = 0; t < 4; ++t) {
            const int idx = t * 256 + tid;
            const int r = idx >> 3, c = idx & 7;
            cp_async16(stg + r * 128 + ((c ^ (r & 7)) << 4),
                       Bg + (size_t)(ch * 128 + r) * Ee + c * 8);
        }
    };

    loadB(0); CP_COMMIT();      // group: A + B chunk 0
    loadB(1); CP_COMMIT();

    float acc[8][2][2][4];
#pragma unroll
    for (int ch = 0; ch < 8; ++ch)
#pragma unroll
        for (int t = 0; t < 2; ++t)
#pragma unroll
            for (int p = 0; p < 2; ++p)
#pragma unroll
                for (int j = 0; j < 4; ++j) acc[ch][t][p][j] = 0.0f;

    uint32_t afr[4][4];

#pragma unroll
    for (int ch = 0; ch < 8; ++ch) {
        CP_WAIT(1);
        __syncthreads();
        if (ch + 2 < 8) { loadB(ch + 2); CP_COMMIT(); } else CP_COMMIT();

        if (ch == 0) {
#pragma unroll
            for (int s = 0; s < 4; ++s) {
                const int row = warp_m * 16 + tsub;
                const int cc = 2 * s + chof;
                ldmat4(afr[s][0], afr[s][1], afr[s][2], afr[s][3],
                       smb + FSM_A + row * 128 + ((cc ^ (row & 7)) << 4));
            }
        }

        const uint32_t stg = smb + FSM_B + (ch % 3) * KCH_B;
#pragma unroll
        for (int s = 0; s < 4; ++s) {
            const int cc = 2 * s + chof;
#pragma unroll
            for (int t = 0; t < 2; ++t) {
                const int rowB = warp_n * 16 + t * 64 + tsub;
                uint32_t q0r, q1r, q2r, q3r;
                ldmat4(q0r, q1r, q2r, q3r,
                       stg + rowB * 128 + ((cc ^ (rowB & 7)) << 4));
                uint32_t be[2] = {q0r, q2r};
                uint32_t bo[2] = {q1r, q3r};
                mma_f16(acc[ch][t][0], afr[s], be);
                mma_f16(acc[ch][t][1], afr[s], bo);
            }
        }
    }

    // ---- mask + scale + softmax ----
    const int r0 = warp_m * 16 + (lane >> 2);
    const int r1 = r0 + 8;
    const int ncol0 = warp_n * 16 + (lane & 3) * 2;
    const int* mrow0 = mask + ((size_t)(b * Ss + q0 + r0)) * Ss;
    const int* mrow1 = mask + ((size_t)(b * Ss + q0 + r1)) * Ss;

    float mx0 = -CUDART_INF_F, mx1 = -CUDART_INF_F;
#pragma unroll
    for (int ch = 0; ch < 8; ++ch)
#pragma unroll
        for (int t = 0; t < 2; ++t)
#pragma unroll
            for (int p = 0; p < 2; ++p) {
                const int n = ch * 128 + t * 64 + p * 8 + ncol0;
                const int2 m0 = *(const int2*)(mrow0 + n);
                const int2 m1 = *(const int2*)(mrow1 + n);
                float* v = acc[ch][t][p];
                v[0] = m0.x ? v[0] * 0.125f : -1e9f;
                v[1] = m0.y ? v[1] * 0.125f : -1e9f;
                v[2] = m1.x ? v[2] * 0.125f : -1e9f;
                v[3] = m1.y ? v[3] * 0.125f : -1e9f;
                mx0 = fmaxf(mx0, fmaxf(v[0], v[1]));
                mx1 = fmaxf(mx1, fmaxf(v[2], v[3]));
            }
    mx0 = fmaxf(mx0, __shfl_xor_sync(0xffffffffu, mx0, 1));
    mx0 = fmaxf(mx0, __shfl_xor_sync(0xffffffffu, mx0, 2));
    mx1 = fmaxf(mx1, __shfl_xor_sync(0xffffffffu, mx1, 1));
    mx1 = fmaxf(mx1, __shfl_xor_sync(0xffffffffu, mx1, 2));
    if ((lane & 3) == 0) { s_red[r0][warp_n] = mx0; s_red[r1][warp_n] = mx1; }
    __syncthreads();
    mx0 = fmaxf(fmaxf(s_red[r0][0], s_red[r0][1]), fmaxf(s_red[r0][2], s_red[r0][3]));
    mx1 = fmaxf(fmaxf(s_red[r1][0], s_red[r1][1]), fmaxf(s_red[r1][2], s_red[r1][3]));
    __syncthreads();

    float sum0 = 0.0f, sum1 = 0.0f;
#pragma unroll
    for (int ch = 0; ch < 8; ++ch)
#pragma unroll
        for (int t = 0; t < 2; ++t)
#pragma unroll
            for (int p = 0; p < 2; ++p) {
                float* v = acc[ch][t][p];
                v[0] = __expf(v[0] - mx0); v[1] = __expf(v[1] - mx0);
                v[2] = __expf(v[2] - mx1); v[3] = __expf(v[3] - mx1);
                sum0 += v[0] + v[1];
                sum1 += v[2] + v[3];
            }
    sum0 += __shfl_xor_sync(0xffffffffu, sum0, 1);
    sum0 += __shfl_xor_sync(0xffffffffu, sum0, 2);
    sum1 += __shfl_xor_sync(0xffffffffu, sum1, 1);
    sum1 += __shfl_xor_sync(0xffffffffu, sum1, 2);
    if ((lane & 3) == 0) { s_red[r0][warp_n] = sum0; s_red[r1][warp_n] = sum1; }
    __syncthreads();
    const float inv0 = 1.0f / (s_red[r0][0] + s_red[r0][1] + s_red[r0][2] + s_red[r0][3]);
    const float inv1 = 1.0f / (s_red[r1][0] + s_red[r1][1] + s_red[r1][2] + s_red[r1][3]);

    __half* P0 = g_Ph + ((size_t)((b * Ss + q0 + r0) * Hh + h)) * Ss;
    __half* P1 = g_Ph + ((size_t)((b * Ss + q0 + r1) * Hh + h)) * Ss;
#pragma unroll
    for (int ch = 0; ch < 8; ++ch)
#pragma unroll
        for (int t = 0; t < 2; ++t)
#pragma unroll
            for (int p = 0; p < 2; ++p) {
                const int n = ch * 128 + t * 64 + p * 8 + ncol0;
                const float* v = acc[ch][t][p];
                __half2 o0, o1;
                o0.x = __float2half_rn(v[0] * inv0); o0.y = __float2half_rn(v[1] * inv0);
                o1.x = __float2half_rn(v[2] * inv1); o1.y = __float2half_rn(v[3] * inv1);
                *(__half2*)(P0 + n) = o0;
                *(__half2*)(P1 + n) = o1;
            }
}

// ---------------------------------------------------------------------------
// Merged fp32 -> fp16 (rn) conversion: grid.y 0..3 = quarters of x, 4..6 = W's.
// Each segment = 262144 float4 -> 524288 half2.
// ---------------------------------------------------------------------------
__global__ void conv_f16_all(const float4* __restrict__ x, __half2* __restrict__ xh,
                             const float4* __restrict__ wq, __half2* __restrict__ wqh,
                             const float4* __restrict__ wk, __half2* __restrict__ wkh,
                             const float4* __restrict__ wo, __half2* __restrict__ woh) {
    const int seg = blockIdx.y;
    const int i = blockIdx.x * blockDim.x + threadIdx.x;
    const float4* s; __half2* d;
    if (seg < 4)      { s = x  + (size_t)seg * 262144; d = xh  + (size_t)seg * 524288; }
    else if (seg == 4){ s = wq; d = wqh; }
    else if (seg == 5){ s = wk; d = wkh; }
    else              { s = wo; d = woh; }
    const float4 v = s[i];
    __half2 h0, h1;
    h0.x = __float2half_rn(v.x); h0.y = __float2half_rn(v.y);
    h1.x = __float2half_rn(v.z); h1.y = __float2half_rn(v.w);
    d[i * 2 + 0] = h0;
    d[i * 2 + 1] = h1;
}

// ---------------------------------------------------------------------------
extern "C" void kernel_launch(void* const* d_in, const int* in_sizes, int n_in,
                              void* d_out, int out_size) {
    const float* x   = (const float*)d_in[0];
    const int*   msk = (const int*)  d_in[1];
    const float* Wq  = (const float*)d_in[2];
    const float* bq  = (const float*)d_in[3];
    const float* Wk  = (const float*)d_in[4];
    const float* bk  = (const float*)d_in[5];
    // d_in[6], d_in[7] = Wv, bv : unused (reference discards V)
    const float* Wo  = (const float*)d_in[8];
    const float* bo  = (const float*)d_in[9];
    float* out = (float*)d_out;

    __half *qh, *kh, *ph, *xh, *wqh, *wkh, *woh;
    cudaGetSymbolAddress((void**)&qh,  g_Qh);
    cudaGetSymbolAddress((void**)&kh,  g_Kh);
    cudaGetSymbolAddress((void**)&ph,  g_Ph);
    cudaGetSymbolAddress((void**)&xh,  g_xh);
    cudaGetSymbolAddress((void**)&wqh, g_Wqh);
    cudaGetSymbolAddress((void**)&wkh, g_Wkh);
    cudaGetSymbolAddress((void**)&woh, g_Woh);

    cudaFuncSetAttribute(gemm_f16,
                         cudaFuncAttributeMaxDynamicSharedMemorySize, GEMM_SMEM);
    cudaFuncSetAttribute(attn_fused,
                         cudaFuncAttributeMaxDynamicSharedMemorySize, FUSED_SMEM);

    // 0) fp32 -> fp16 conversion (one launch)
    {
        dim3 grid(1024, 7);
        conv_f16_all<<<grid, 256>>>((const float4*)x,  (__half2*)xh,
                                    (const float4*)Wq, (__half2*)wqh,
                                    (const float4*)Wk, (__half2*)wkh,
                                    (const float4*)Wo, (__half2*)woh);
    }

    // 1) Q + K projections in ONE launch (z=0 -> Q, z=1 -> K), fp16 outputs
    {
        dim3 grid(Ee / BNt, (Bq * Ss) / BMt, 2);   // (8, 32, 2)
        gemm_f16<<<grid, 256, GEMM_SMEM>>>(xh, wqh, bq, nullptr, qh,
                                           wkh, bk, kh, 1);
    }

    // 2) Fused scores + mask + softmax -> g_Ph (fp16)
    {
        dim3 grid(Ss / 32, Bq * Hh);               // (32, 64)
        attn_fused<<<grid, 256, FUSED_SMEM>>>(msk);
    }

    // 3) Output projection: P[65536,1024] @ Wo^T + bo -> fp32 out
    {
        const int M = Bq * Ss * Hh;                // 65536
        dim3 grid(Ee / BNt, M / BMt, 1);           // (8, 512)
        gemm_f16<<<grid, 256, GEMM_SMEM>>>(ph, woh, bo, out, nullptr,
                                           woh, bo, nullptr, 0);
    }
}